// round 1
// baseline (speedup 1.0000x reference)
#include <cuda_runtime.h>
#include <math.h>

// Problem constants
#define B2   2
#define L2   1024
#define D2   768
#define H2   12
#define DH   64
#define BH   (B2*H2)        // 24
#define BL   (B2*L2)        // 2048
#define N3D  (3*D2)         // 2304
#define CHK  128            // chunk length
#define NC   (L2/CHK)       // 8
#define OUT_ELEMS (BL*D2)   // 1572864

// ---------------- scratch (device globals; no allocation allowed) ----------
__device__ float g_xn[BL*D2];
__device__ float g_qkv[BL*N3D];
__device__ float g_qf[BH*L2*DH];
__device__ float g_kf[BH*L2*DH];
__device__ float g_vf[BH*L2*DH];
__device__ float g_kv[BH*NC*DH*DH];
__device__ float g_ksum[BH*NC*DH];
__device__ float g_sprev[BH*NC*DH*DH];
__device__ float g_ksp[BH*NC*DH];
__device__ float g_attn[BL*D2];

// ---------------- LayerNorm: one block per row --------------------------
__global__ void ln_kernel(const float* __restrict__ x,
                          const float* __restrict__ g,
                          const float* __restrict__ b,
                          float* __restrict__ xn) {
    int row = blockIdx.x;
    int tid = threadIdx.x;  // 256
    const float* xr = x + row * D2;
    float v0 = xr[tid], v1 = xr[tid + 256], v2 = xr[tid + 512];
    float s  = v0 + v1 + v2;
    float sq = v0*v0 + v1*v1 + v2*v2;
    #pragma unroll
    for (int o = 16; o; o >>= 1) {
        s  += __shfl_xor_sync(0xffffffffu, s,  o);
        sq += __shfl_xor_sync(0xffffffffu, sq, o);
    }
    __shared__ float ss[8], sqs[8];
    if ((tid & 31) == 0) { ss[tid >> 5] = s; sqs[tid >> 5] = sq; }
    __syncthreads();
    float ts = 0.f, tq = 0.f;
    #pragma unroll
    for (int w = 0; w < 8; w++) { ts += ss[w]; tq += sqs[w]; }
    float mean = ts * (1.f / D2);
    float var  = tq * (1.f / D2) - mean * mean;
    float inv  = rsqrtf(var + 1e-5f);
    float* xo = xn + row * D2;
    xo[tid]       = (v0 - mean) * inv * g[tid]       + b[tid];
    xo[tid + 256] = (v1 - mean) * inv * g[tid + 256] + b[tid + 256];
    xo[tid + 512] = (v2 - mean) * inv * g[tid + 512] + b[tid + 512];
}

// ---------------- Tiled fp32 GEMM: C = A[M,K] @ W[K,N] + bias, optional sigmoid
// BM=BN=128, BK=8, 256 threads, 8x8 per thread. M%128==0, N%128==0, K%8==0.
template <int EPI>   // 0 = none, 1 = sigmoid
__global__ void gemm_kernel(const float* __restrict__ A,
                            const float* __restrict__ W,
                            const float* __restrict__ bias,
                            float* __restrict__ C,
                            int M, int N, int K) {
    __shared__ float As[8][128];
    __shared__ float Bs[8][128];
    int tid = threadIdx.x;
    int tx = tid & 15, ty = tid >> 4;
    int bx = blockIdx.x, by = blockIdx.y;
    const float* Ap = A + (size_t)(by * 128) * K;
    const float* Wp = W + bx * 128;
    int a_row = tid >> 1;
    int a_col = (tid & 1) << 2;
    int b_row = tid >> 5;
    int b_col = (tid & 31) << 2;
    float acc[8][8];
    #pragma unroll
    for (int i = 0; i < 8; i++)
        #pragma unroll
        for (int j = 0; j < 8; j++) acc[i][j] = 0.f;

    for (int k0 = 0; k0 < K; k0 += 8) {
        float4 av = *(const float4*)(Ap + (size_t)a_row * K + k0 + a_col);
        As[a_col + 0][a_row] = av.x;
        As[a_col + 1][a_row] = av.y;
        As[a_col + 2][a_row] = av.z;
        As[a_col + 3][a_row] = av.w;
        float4 bv = *(const float4*)(Wp + (size_t)(k0 + b_row) * N + b_col);
        *(float4*)&Bs[b_row][b_col] = bv;
        __syncthreads();
        #pragma unroll
        for (int kk = 0; kk < 8; kk++) {
            float af[8], bf[8];
            *(float4*)&af[0] = *(const float4*)&As[kk][ty * 8];
            *(float4*)&af[4] = *(const float4*)&As[kk][ty * 8 + 4];
            *(float4*)&bf[0] = *(const float4*)&Bs[kk][tx * 8];
            *(float4*)&bf[4] = *(const float4*)&Bs[kk][tx * 8 + 4];
            #pragma unroll
            for (int i = 0; i < 8; i++)
                #pragma unroll
                for (int j = 0; j < 8; j++) acc[i][j] += af[i] * bf[j];
        }
        __syncthreads();
    }
    #pragma unroll
    for (int i = 0; i < 8; i++) {
        int row = by * 128 + ty * 8 + i;
        #pragma unroll
        for (int j = 0; j < 8; j++) {
            int col = bx * 128 + tx * 8 + j;
            float c = acc[i][j] + bias[col];
            if (EPI == 1) c = 1.f / (1.f + expf(-c));
            C[(size_t)row * N + col] = c;
        }
    }
}

// ---------------- prep: split qkv, apply gate to k, elu+1, head layout ----
__global__ void prep_kernel(const float* __restrict__ qkv,
                            const float* __restrict__ gate,
                            float* __restrict__ qf,
                            float* __restrict__ kf,
                            float* __restrict__ vf) {
    int idx = blockIdx.x * 256 + threadIdx.x;     // 0 .. BL*D2
    int bl = idx / D2;
    int c  = idx - bl * D2;
    int h = c >> 6, d = c & 63;
    int b = bl >> 10, l = bl & 1023;
    float q = qkv[(size_t)bl * N3D + c];
    float k = qkv[(size_t)bl * N3D + D2 + c] * gate[idx];
    float v = qkv[(size_t)bl * N3D + 2 * D2 + c];
    int o = ((b * H2 + h) * L2 + l) * DH + d;
    qf[o] = (q > 0.f) ? (q + 1.f) : expf(q);
    kf[o] = (k > 0.f) ? (k + 1.f) : expf(k);
    vf[o] = v;
}

// ---------------- per-chunk K^T V (64x64) and ksum (64) -------------------
__global__ void chunk_kv_kernel(const float* __restrict__ kf,
                                const float* __restrict__ vf,
                                float* __restrict__ kv,
                                float* __restrict__ ksum) {
    __shared__ float Ks[32][64];
    __shared__ float Vs[32][64];
    int c = blockIdx.x, bh = blockIdx.y;
    int tid = threadIdx.x;   // 256
    const float* kp = kf + (size_t)(bh * L2 + c * CHK) * DH;
    const float* vp = vf + (size_t)(bh * L2 + c * CHK) * DH;
    int j = tid & 63;
    int ibase = tid >> 6;    // 0..3
    float acc[16];
    #pragma unroll
    for (int r = 0; r < 16; r++) acc[r] = 0.f;
    float ks = 0.f;
    for (int tt = 0; tt < 4; tt++) {
        for (int i = tid; i < 512; i += 256) {
            int row = i >> 4, col = (i & 15) << 2;
            *(float4*)&Ks[row][col] = *(const float4*)(kp + (size_t)(tt*32 + row)*DH + col);
            *(float4*)&Vs[row][col] = *(const float4*)(vp + (size_t)(tt*32 + row)*DH + col);
        }
        __syncthreads();
        #pragma unroll 4
        for (int t = 0; t < 32; t++) {
            float vj = Vs[t][j];
            #pragma unroll
            for (int r = 0; r < 16; r++)
                acc[r] += Ks[t][ibase + 4 * r] * vj;
        }
        if (tid < 64) {
            #pragma unroll 4
            for (int t = 0; t < 32; t++) ks += Ks[t][tid];
        }
        __syncthreads();
    }
    float* kvp = kv + (size_t)(bh * NC + c) * DH * DH;
    #pragma unroll
    for (int r = 0; r < 16; r++)
        kvp[(ibase + 4 * r) * DH + j] = acc[r];
    if (tid < 64) ksum[(bh * NC + c) * DH + tid] = ks;
}

// ---------------- exclusive prefix over chunks ----------------------------
__global__ void scan_kernel(const float* __restrict__ kv,
                            const float* __restrict__ ksum,
                            float* __restrict__ sprev,
                            float* __restrict__ ksp) {
    int bh = blockIdx.x;
    int tid = threadIdx.x;  // 256
    #pragma unroll
    for (int r = 0; r < 16; r++) {
        int e = tid + 256 * r;
        float acc = 0.f;
        #pragma unroll
        for (int c = 0; c < NC; c++) {
            size_t o = (size_t)(bh * NC + c) * DH * DH + e;
            sprev[o] = acc;
            acc += kv[o];
        }
    }
    if (tid < 64) {
        float acc = 0.f;
        #pragma unroll
        for (int c = 0; c < NC; c++) {
            size_t o = (size_t)(bh * NC + c) * DH + tid;
            ksp[o] = acc;
            acc += ksum[o];
        }
    }
}

// ---------------- per-chunk attention output ------------------------------
// smem layout (floats): Q 128*65 | K 128*65 | V 128*64 | A 128*129 | S 64*64 | ksp 64 | den 128
#define SM_Q   0
#define SM_K   (128*65)
#define SM_V   (SM_K + 128*65)
#define SM_A   (SM_V + 128*64)
#define SM_S   (SM_A + 128*129)
#define SM_KS  (SM_S + 64*64)
#define SM_DEN (SM_KS + 64)
#define ATTN_SMEM_FLOATS (SM_DEN + 128)

__global__ void attn_kernel(const float* __restrict__ qf,
                            const float* __restrict__ kf,
                            const float* __restrict__ vf,
                            const float* __restrict__ sprev,
                            const float* __restrict__ ksp,
                            float* __restrict__ attn_out) {
    extern __shared__ float sm[];
    float* Qs = sm + SM_Q;
    float* Ks = sm + SM_K;
    float* Vs = sm + SM_V;
    float* As = sm + SM_A;
    float* Ss = sm + SM_S;
    float* Kp = sm + SM_KS;
    float* Dn = sm + SM_DEN;
    int c = blockIdx.x, bh = blockIdx.y;
    int tid = threadIdx.x;   // 256
    const float* qp = qf + (size_t)(bh * L2 + c * CHK) * DH;
    const float* kp = kf + (size_t)(bh * L2 + c * CHK) * DH;
    const float* vp = vf + (size_t)(bh * L2 + c * CHK) * DH;
    // load Q,K padded (stride 65), V unpadded
    for (int i = tid; i < 2048; i += 256) {       // 2048 float4 = 8192 floats
        int row = i >> 4, col = (i & 15) << 2;
        float4 q4 = *(const float4*)(qp + (size_t)row * DH + col);
        float4 k4 = *(const float4*)(kp + (size_t)row * DH + col);
        float* qd = Qs + row * 65 + col;
        float* kd = Ks + row * 65 + col;
        qd[0]=q4.x; qd[1]=q4.y; qd[2]=q4.z; qd[3]=q4.w;
        kd[0]=k4.x; kd[1]=k4.y; kd[2]=k4.z; kd[3]=k4.w;
        *(float4*)(Vs + row * DH + col) = *(const float4*)(vp + (size_t)row * DH + col);
    }
    {
        const float4* sp = (const float4*)(sprev + (size_t)(bh * NC + c) * DH * DH);
        for (int i = tid; i < 1024; i += 256) ((float4*)Ss)[i] = sp[i];
        if (tid < 16)
            ((float4*)Kp)[tid] = ((const float4*)(ksp + (size_t)(bh * NC + c) * DH))[tid];
    }
    __syncthreads();
    // A = (Q K^T) lower-triangular (incl diag), zeros above
    {
        int aj = tid & 127;
        int ib = tid >> 7;      // 0/1
        for (int r = 0; r < 64; r++) {
            int ai = ib + 2 * r;
            float acc = 0.f;
            if (aj <= ai) {
                const float* qr = Qs + ai * 65;
                const float* kr = Ks + aj * 65;
                #pragma unroll
                for (int d = 0; d < 64; d++) acc += qr[d] * kr[d];
            }
            As[ai * 129 + aj] = acc;
        }
    }
    __syncthreads();
    // rowsum + den
    if (tid < 128) {
        float s = 0.f;
        const float* ar = As + tid * 129;
        for (int j = 0; j <= tid; j++) s += ar[j];
        const float* qr = Qs + tid * 65;
        float qk = 0.f;
        #pragma unroll
        for (int d = 0; d < 64; d++) qk += qr[d] * Kp[d];
        Dn[tid] = s + qk + 1e-6f;
    }
    __syncthreads();
    // O = A @ V + Q @ S_prev ; divide by den ; write (B,L,D)
    {
        int oj = tid & 63;
        int ob = tid >> 6;   // 0..3
        int b = bh / H2, h = bh - b * H2;
        for (int r = 0; r < 32; r++) {
            int oi = ob + 4 * r;
            float acc = 0.f;
            const float* ar = As + oi * 129;
            for (int t = 0; t <= oi; t++) acc += ar[t] * Vs[t * DH + oj];
            const float* qr = Qs + oi * 65;
            #pragma unroll
            for (int d = 0; d < 64; d++) acc += qr[d] * Ss[d * DH + oj];
            int l = c * CHK + oi;
            attn_out[(size_t)(b * L2 + l) * D2 + h * DH + oj] = acc / Dn[oi];
        }
    }
}

// ---------------- launch ---------------------------------------------------
extern "C" void kernel_launch(void* const* d_in, const int* in_sizes, int n_in,
                              void* d_out, int out_size) {
    const float* x      = (const float*)d_in[0];
    const float* W_qkv  = (const float*)d_in[1];
    const float* b_qkv  = (const float*)d_in[2];
    const float* W_gate = (const float*)d_in[3];
    const float* b_gate = (const float*)d_in[4];
    const float* W_proj = (const float*)d_in[5];
    const float* b_proj = (const float*)d_in[6];
    const float* ln_g   = (const float*)d_in[7];
    const float* ln_b   = (const float*)d_in[8];
    float* out  = (float*)d_out;           // proj output
    float* gate = out + OUT_ELEMS;         // gate output (2nd return value)

    float *p_xn, *p_qkv, *p_qf, *p_kf, *p_vf, *p_kv, *p_ksum, *p_sprev, *p_ksp, *p_attn;
    cudaGetSymbolAddress((void**)&p_xn,    g_xn);
    cudaGetSymbolAddress((void**)&p_qkv,   g_qkv);
    cudaGetSymbolAddress((void**)&p_qf,    g_qf);
    cudaGetSymbolAddress((void**)&p_kf,    g_kf);
    cudaGetSymbolAddress((void**)&p_vf,    g_vf);
    cudaGetSymbolAddress((void**)&p_kv,    g_kv);
    cudaGetSymbolAddress((void**)&p_ksum,  g_ksum);
    cudaGetSymbolAddress((void**)&p_sprev, g_sprev);
    cudaGetSymbolAddress((void**)&p_ksp,   g_ksp);
    cudaGetSymbolAddress((void**)&p_attn,  g_attn);

    // 1. LayerNorm
    ln_kernel<<<BL, 256>>>(x, ln_g, ln_b, p_xn);

    // 2. qkv = xn @ W_qkv + b_qkv
    gemm_kernel<0><<<dim3(N3D / 128, BL / 128), 256>>>(p_xn, W_qkv, b_qkv, p_qkv, BL, N3D, D2);

    // 3. gate = sigmoid(x @ W_gate + b_gate)  (on raw x) -> second output
    gemm_kernel<1><<<dim3(D2 / 128, BL / 128), 256>>>(x, W_gate, b_gate, gate, BL, D2, D2);

    // 4. split / gate-k / elu+1 / head layout
    prep_kernel<<<(BL * D2) / 256, 256>>>(p_qkv, gate, p_qf, p_kf, p_vf);

    // 5. per-chunk K^T V and ksum
    chunk_kv_kernel<<<dim3(NC, BH), 256>>>(p_kf, p_vf, p_kv, p_ksum);

    // 6. exclusive prefix over chunks
    scan_kernel<<<BH, 256>>>(p_kv, p_ksum, p_sprev, p_ksp);

    // 7. per-chunk attention
    static_assert(ATTN_SMEM_FLOATS * 4 < 227 * 1024, "smem");
    cudaFuncSetAttribute(attn_kernel, cudaFuncAttributeMaxDynamicSharedMemorySize,
                         ATTN_SMEM_FLOATS * 4);
    attn_kernel<<<dim3(NC, BH), 256, ATTN_SMEM_FLOATS * 4>>>(p_qf, p_kf, p_vf, p_sprev, p_ksp, p_attn);

    // 8. out = attn @ W_proj + b_proj
    gemm_kernel<0><<<dim3(D2 / 128, BL / 128), 256>>>(p_attn, W_proj, b_proj, out, BL, D2, D2);
}

// round 3
// speedup vs baseline: 1.7367x; 1.7367x over previous
#include <cuda_runtime.h>
#include <cuda_bf16.h>
#include <math.h>
#include <stdint.h>

// Problem constants
#define B2   2
#define L2   1024
#define D2   768
#define H2   12
#define DH   64
#define BH   (B2*H2)        // 24
#define BL   (B2*L2)        // 2048
#define N3D  (3*D2)         // 2304
#define CHK  128            // chunk length
#define NC   (L2/CHK)       // 8
#define GK   768            // shared K dim of all GEMMs
#define OUT_ELEMS (BL*D2)   // 1572864

// ---------------- scratch (device globals; no allocation allowed) ----------
__device__ float g_xn[BL*D2];
__device__ float g_qkv[BL*N3D];
__device__ float g_qf[BH*L2*DH];
__device__ float g_kf[BH*L2*DH];
__device__ float g_vf[BH*L2*DH];
__device__ float g_kv[BH*NC*DH*DH];
__device__ float g_ksum[BH*NC*DH];
__device__ float g_sprev[BH*NC*DH*DH];
__device__ float g_ksp[BH*NC*DH];
__device__ float g_attn[BL*D2];
__device__ float g_wt_qkv[N3D*GK];
__device__ float g_wt_gate[D2*GK];
__device__ float g_wt_proj[D2*GK];

// =================== helpers ===============================================
__device__ __forceinline__ uint32_t smem_u32(const void* p) {
    uint32_t a;
    asm("{ .reg .u64 t; cvta.to.shared.u64 t, %1; cvt.u32.u64 %0, t; }"
        : "=r"(a) : "l"(p));
    return a;
}
__device__ __forceinline__ uint32_t sw128(uint32_t off) {
    return off ^ ((off >> 3) & 0x70);
}

#define LDSM4(r0, r1, r2, r3, addr) \
    asm volatile("ldmatrix.sync.aligned.m8n8.x4.shared.b16 {%0,%1,%2,%3}, [%4];" \
        : "=r"(r0), "=r"(r1), "=r"(r2), "=r"(r3) : "r"(addr))

#define MMA_BF16(d, a, b) \
    asm volatile("mma.sync.aligned.m16n8k16.row.col.f32.bf16.bf16.f32 " \
        "{%0,%1,%2,%3},{%4,%5,%6,%7},{%8,%9},{%0,%1,%2,%3};" \
        : "+f"((d)[0]), "+f"((d)[1]), "+f"((d)[2]), "+f"((d)[3]) \
        : "r"((a)[0]), "r"((a)[1]), "r"((a)[2]), "r"((a)[3]), \
          "r"((b)[0]), "r"((b)[1]))

__device__ __forceinline__ void split_pair(float x, float y,
                                           uint32_t& hi, uint32_t& lo) {
    __nv_bfloat16 hx = __float2bfloat16(x);
    __nv_bfloat16 hy = __float2bfloat16(y);
    float rx = x - __bfloat162float(hx);
    float ry = y - __bfloat162float(hy);
    __nv_bfloat16 lx = __float2bfloat16(rx);
    __nv_bfloat16 ly = __float2bfloat16(ry);
    hi = ((uint32_t)__bfloat16_as_ushort(hy) << 16) | (uint32_t)__bfloat16_as_ushort(hx);
    lo = ((uint32_t)__bfloat16_as_ushort(ly) << 16) | (uint32_t)__bfloat16_as_ushort(lx);
}

// ---------------- LayerNorm: one block per row --------------------------
__global__ void ln_kernel(const float* __restrict__ x,
                          const float* __restrict__ g,
                          const float* __restrict__ b,
                          float* __restrict__ xn) {
    int row = blockIdx.x;
    int tid = threadIdx.x;  // 256
    const float* xr = x + row * D2;
    float v0 = xr[tid], v1 = xr[tid + 256], v2 = xr[tid + 512];
    float s  = v0 + v1 + v2;
    float sq = v0*v0 + v1*v1 + v2*v2;
    #pragma unroll
    for (int o = 16; o; o >>= 1) {
        s  += __shfl_xor_sync(0xffffffffu, s,  o);
        sq += __shfl_xor_sync(0xffffffffu, sq, o);
    }
    __shared__ float ss[8], sqs[8];
    if ((tid & 31) == 0) { ss[tid >> 5] = s; sqs[tid >> 5] = sq; }
    __syncthreads();
    float ts = 0.f, tq = 0.f;
    #pragma unroll
    for (int w = 0; w < 8; w++) { ts += ss[w]; tq += sqs[w]; }
    float mean = ts * (1.f / D2);
    float var  = tq * (1.f / D2) - mean * mean;
    float inv  = rsqrtf(var + 1e-5f);
    float* xo = xn + row * D2;
    xo[tid]       = (v0 - mean) * inv * g[tid]       + b[tid];
    xo[tid + 256] = (v1 - mean) * inv * g[tid + 256] + b[tid + 256];
    xo[tid + 512] = (v2 - mean) * inv * g[tid + 512] + b[tid + 512];
}

// ---------------- W[K,N] -> Wt[N,K] transpose ------------------------------
__global__ void transpose_kernel(const float* __restrict__ W,
                                 float* __restrict__ Wt, int K, int N) {
    __shared__ float t[32][33];
    int n0 = blockIdx.x * 32, k0 = blockIdx.y * 32;
    int tx = threadIdx.x, ty = threadIdx.y;   // (32, 8)
    #pragma unroll
    for (int r = ty; r < 32; r += 8)
        t[r][tx] = W[(size_t)(k0 + r) * N + n0 + tx];
    __syncthreads();
    #pragma unroll
    for (int r = ty; r < 32; r += 8)
        Wt[(size_t)(n0 + r) * K + k0 + tx] = t[tx][r];
}

// ---------------- bf16x3 mma.sync GEMM -------------------------------------
// C[M,N] = A[M,768] @ Wt[N,768]^T + bias. BM=BN=128, BK=64, double buffered.
// SMEM stage (65536 B): Ah 16K | Al 16K | Bh 16K | Bl 16K. Rows = 128B, SW128.
#define BKC 64
#define STG_A_HI 0
#define STG_A_LO 16384
#define STG_B_HI 32768
#define STG_B_LO 49152
#define GEMM_STAGE_BYTES 65536
#define GEMM_SMEM_BYTES  (2 * GEMM_STAGE_BYTES)
#define NCHUNK (GK / BKC)   // 12

// store one staged register set (8 A float4 + 8 B float4) into smem stage
__device__ __forceinline__ void sts_stage(char* smem, int stage, int tid,
                                          const float4* ar, const float4* br) {
    char* base = smem + stage * GEMM_STAGE_BYTES;
    #pragma unroll
    for (int i = 0; i < 8; i++) {
        int idx = tid + 256 * i;         // 0..2047
        int row = idx >> 4;              // 0..127
        int col4 = (idx & 15) << 2;      // 0..60 step 4
        uint32_t off = sw128((uint32_t)(row * 128 + col4 * 2));
        uint32_t h0, l0, h1, l1;
        split_pair(ar[i].x, ar[i].y, h0, l0);
        split_pair(ar[i].z, ar[i].w, h1, l1);
        *(uint2*)(base + STG_A_HI + off) = make_uint2(h0, h1);
        *(uint2*)(base + STG_A_LO + off) = make_uint2(l0, l1);
        split_pair(br[i].x, br[i].y, h0, l0);
        split_pair(br[i].z, br[i].w, h1, l1);
        *(uint2*)(base + STG_B_HI + off) = make_uint2(h0, h1);
        *(uint2*)(base + STG_B_LO + off) = make_uint2(l0, l1);
    }
}

template <int EPI>   // 0 = none, 1 = sigmoid
__global__ void __launch_bounds__(256, 1) mma_gemm_kernel(
    const float* __restrict__ A,
    const float* __restrict__ Bt,
    const float* __restrict__ bias,
    float* __restrict__ C, int Nld)
{
    extern __shared__ char smem[];
    uint32_t sb = smem_u32(smem);
    int tid  = threadIdx.x;
    int wid  = tid >> 5, lane = tid & 31;
    int wm   = wid >> 2, wn = wid & 3;        // warp grid 2x4
    int m0   = wm * 64;                       // warp tile 64x32
    int n0   = wn * 32;
    int lr   = lane & 7, g = lane >> 3;       // ldmatrix addressing
    int arow = ((g & 1) << 3) + lr;
    int acolb = (g >> 1) << 4;                // 0 or 16 bytes
    int brow = ((g >> 1) << 3) + lr;
    int bcolb = (g & 1) << 4;

    const float* Ap = A  + (size_t)blockIdx.y * 128 * GK;
    const float* Bp = Bt + (size_t)blockIdx.x * 128 * GK;

    float acc[4][4][4];
    #pragma unroll
    for (int mt = 0; mt < 4; mt++)
        #pragma unroll
        for (int nt = 0; nt < 4; nt++)
            #pragma unroll
            for (int q = 0; q < 4; q++) acc[mt][nt][q] = 0.f;

    // prologue: load + store chunk 0
    float4 ar[8], br[8];
    #pragma unroll
    for (int i = 0; i < 8; i++) {
        int idx = tid + 256 * i;
        int row = idx >> 4;
        int col4 = (idx & 15) << 2;
        ar[i] = *(const float4*)(Ap + (size_t)row * GK + col4);
        br[i] = *(const float4*)(Bp + (size_t)row * GK + col4);
    }
    sts_stage(smem, 0, tid, ar, br);
    __syncthreads();

    for (int c = 0; c < NCHUNK; c++) {
        int stage = c & 1;
        if (c + 1 < NCHUNK) {
            int k0 = (c + 1) * BKC;
            #pragma unroll
            for (int i = 0; i < 8; i++) {
                int idx = tid + 256 * i;
                int row = idx >> 4;
                int col4 = (idx & 15) << 2;
                ar[i] = *(const float4*)(Ap + (size_t)row * GK + k0 + col4);
                br[i] = *(const float4*)(Bp + (size_t)row * GK + k0 + col4);
            }
        }
        uint32_t sA  = sb + stage * GEMM_STAGE_BYTES;
        uint32_t sAl = sA + STG_A_LO;
        uint32_t sBh = sA + STG_B_HI;
        uint32_t sBl = sA + STG_B_LO;
        #pragma unroll
        for (int kt = 0; kt < 4; kt++) {
            // B fragments: 4 ntiles via 2 ldmatrix.x4 per matrix
            uint32_t bh[4][2], bl[4][2];
            #pragma unroll
            for (int t = 0; t < 2; t++) {
                uint32_t boff = sw128((uint32_t)((n0 + t * 16 + brow) * 128 + kt * 32 + bcolb));
                LDSM4(bh[2*t][0], bh[2*t][1], bh[2*t+1][0], bh[2*t+1][1], sBh + boff);
                LDSM4(bl[2*t][0], bl[2*t][1], bl[2*t+1][0], bl[2*t+1][1], sBl + boff);
            }
            #pragma unroll
            for (int mt = 0; mt < 4; mt++) {
                uint32_t aoff = sw128((uint32_t)((m0 + mt * 16 + arow) * 128 + kt * 32 + acolb));
                uint32_t ah[4], al[4];
                LDSM4(ah[0], ah[1], ah[2], ah[3], sA  + aoff);
                LDSM4(al[0], al[1], al[2], al[3], sAl + aoff);
                #pragma unroll
                for (int nt = 0; nt < 4; nt++) {
                    MMA_BF16(acc[mt][nt], ah, bh[nt]);
                    MMA_BF16(acc[mt][nt], ah, bl[nt]);
                    MMA_BF16(acc[mt][nt], al, bh[nt]);
                }
            }
        }
        __syncthreads();
        if (c + 1 < NCHUNK) {
            sts_stage(smem, stage ^ 1, tid, ar, br);
            __syncthreads();
        }
    }

    // epilogue
    int rbase = blockIdx.y * 128 + m0 + (lane >> 2);
    int cbase = blockIdx.x * 128 + n0 + ((lane & 3) << 1);
    #pragma unroll
    for (int mt = 0; mt < 4; mt++) {
        #pragma unroll
        for (int nt = 0; nt < 4; nt++) {
            int col = cbase + nt * 8;
            float b0 = bias[col], b1 = bias[col + 1];
            #pragma unroll
            for (int h = 0; h < 2; h++) {
                int row = rbase + mt * 16 + h * 8;
                float o0 = acc[mt][nt][2*h + 0] + b0;
                float o1 = acc[mt][nt][2*h + 1] + b1;
                if (EPI == 1) {
                    o0 = 1.f / (1.f + expf(-o0));
                    o1 = 1.f / (1.f + expf(-o1));
                }
                *(float2*)(C + (size_t)row * Nld + col) = make_float2(o0, o1);
            }
        }
    }
}

// ---------------- prep: split qkv, apply gate to k, elu+1, head layout ----
__global__ void prep_kernel(const float* __restrict__ qkv,
                            const float* __restrict__ gate,
                            float* __restrict__ qf,
                            float* __restrict__ kf,
                            float* __restrict__ vf) {
    int idx = blockIdx.x * 256 + threadIdx.x;     // 0 .. BL*D2
    int bl = idx / D2;
    int c  = idx - bl * D2;
    int h = c >> 6, d = c & 63;
    int b = bl >> 10, l = bl & 1023;
    float q = qkv[(size_t)bl * N3D + c];
    float k = qkv[(size_t)bl * N3D + D2 + c] * gate[idx];
    float v = qkv[(size_t)bl * N3D + 2 * D2 + c];
    int o = ((b * H2 + h) * L2 + l) * DH + d;
    qf[o] = (q > 0.f) ? (q + 1.f) : expf(q);
    kf[o] = (k > 0.f) ? (k + 1.f) : expf(k);
    vf[o] = v;
}

// ---------------- per-chunk K^T V (64x64) and ksum (64) -------------------
__global__ void chunk_kv_kernel(const float* __restrict__ kf,
                                const float* __restrict__ vf,
                                float* __restrict__ kv,
                                float* __restrict__ ksum) {
    __shared__ float Ks[32][64];
    __shared__ float Vs[32][64];
    int c = blockIdx.x, bh = blockIdx.y;
    int tid = threadIdx.x;   // 256
    const float* kp = kf + (size_t)(bh * L2 + c * CHK) * DH;
    const float* vp = vf + (size_t)(bh * L2 + c * CHK) * DH;
    int j = tid & 63;
    int ibase = tid >> 6;    // 0..3
    float acc[16];
    #pragma unroll
    for (int r = 0; r < 16; r++) acc[r] = 0.f;
    float ks = 0.f;
    for (int tt = 0; tt < 4; tt++) {
        for (int i = tid; i < 512; i += 256) {
            int row = i >> 4, col = (i & 15) << 2;
            *(float4*)&Ks[row][col] = *(const float4*)(kp + (size_t)(tt*32 + row)*DH + col);
            *(float4*)&Vs[row][col] = *(const float4*)(vp + (size_t)(tt*32 + row)*DH + col);
        }
        __syncthreads();
        #pragma unroll 4
        for (int t = 0; t < 32; t++) {
            float vj = Vs[t][j];
            #pragma unroll
            for (int r = 0; r < 16; r++)
                acc[r] += Ks[t][ibase + 4 * r] * vj;
        }
        if (tid < 64) {
            #pragma unroll 4
            for (int t = 0; t < 32; t++) ks += Ks[t][tid];
        }
        __syncthreads();
    }
    float* kvp = kv + (size_t)(bh * NC + c) * DH * DH;
    #pragma unroll
    for (int r = 0; r < 16; r++)
        kvp[(ibase + 4 * r) * DH + j] = acc[r];
    if (tid < 64) ksum[(bh * NC + c) * DH + tid] = ks;
}

// ---------------- exclusive prefix over chunks ----------------------------
__global__ void scan_kernel(const float* __restrict__ kv,
                            const float* __restrict__ ksum,
                            float* __restrict__ sprev,
                            float* __restrict__ ksp) {
    int bh = blockIdx.x;
    int tid = threadIdx.x;  // 256
    #pragma unroll
    for (int r = 0; r < 16; r++) {
        int e = tid + 256 * r;
        float acc = 0.f;
        #pragma unroll
        for (int c = 0; c < NC; c++) {
            size_t o = (size_t)(bh * NC + c) * DH * DH + e;
            sprev[o] = acc;
            acc += kv[o];
        }
    }
    if (tid < 64) {
        float acc = 0.f;
        #pragma unroll
        for (int c = 0; c < NC; c++) {
            size_t o = (size_t)(bh * NC + c) * DH + tid;
            ksp[o] = acc;
            acc += ksum[o];
        }
    }
}

// ---------------- per-chunk attention output ------------------------------
#define SM_Q   0
#define SM_K   (128*65)
#define SM_V   (SM_K + 128*65)
#define SM_A   (SM_V + 128*64)
#define SM_S   (SM_A + 128*129)
#define SM_KS  (SM_S + 64*64)
#define SM_DEN (SM_KS + 64)
#define ATTN_SMEM_FLOATS (SM_DEN + 128)

__global__ void attn_kernel(const float* __restrict__ qf,
                            const float* __restrict__ kf,
                            const float* __restrict__ vf,
                            const float* __restrict__ sprev,
                            const float* __restrict__ ksp,
                            float* __restrict__ attn_out) {
    extern __shared__ float sm[];
    float* Qs = sm + SM_Q;
    float* Ks = sm + SM_K;
    float* Vs = sm + SM_V;
    float* As = sm + SM_A;
    float* Ss = sm + SM_S;
    float* Kp = sm + SM_KS;
    float* Dn = sm + SM_DEN;
    int c = blockIdx.x, bh = blockIdx.y;
    int tid = threadIdx.x;   // 256
    const float* qp = qf + (size_t)(bh * L2 + c * CHK) * DH;
    const float* kp = kf + (size_t)(bh * L2 + c * CHK) * DH;
    const float* vp = vf + (size_t)(bh * L2 + c * CHK) * DH;
    for (int i = tid; i < 2048; i += 256) {
        int row = i >> 4, col = (i & 15) << 2;
        float4 q4 = *(const float4*)(qp + (size_t)row * DH + col);
        float4 k4 = *(const float4*)(kp + (size_t)row * DH + col);
        float* qd = Qs + row * 65 + col;
        float* kd = Ks + row * 65 + col;
        qd[0]=q4.x; qd[1]=q4.y; qd[2]=q4.z; qd[3]=q4.w;
        kd[0]=k4.x; kd[1]=k4.y; kd[2]=k4.z; kd[3]=k4.w;
        *(float4*)(Vs + row * DH + col) = *(const float4*)(vp + (size_t)row * DH + col);
    }
    {
        const float4* sp = (const float4*)(sprev + (size_t)(bh * NC + c) * DH * DH);
        for (int i = tid; i < 1024; i += 256) ((float4*)Ss)[i] = sp[i];
        if (tid < 16)
            ((float4*)Kp)[tid] = ((const float4*)(ksp + (size_t)(bh * NC + c) * DH))[tid];
    }
    __syncthreads();
    {
        int aj = tid & 127;
        int ib = tid >> 7;
        for (int r = 0; r < 64; r++) {
            int ai = ib + 2 * r;
            float acc = 0.f;
            if (aj <= ai) {
                const float* qr = Qs + ai * 65;
                const float* kr = Ks + aj * 65;
                #pragma unroll
                for (int d = 0; d < 64; d++) acc += qr[d] * kr[d];
            }
            As[ai * 129 + aj] = acc;
        }
    }
    __syncthreads();
    if (tid < 128) {
        float s = 0.f;
        const float* ar = As + tid * 129;
        for (int j = 0; j <= tid; j++) s += ar[j];
        const float* qr = Qs + tid * 65;
        float qk = 0.f;
        #pragma unroll
        for (int d = 0; d < 64; d++) qk += qr[d] * Kp[d];
        Dn[tid] = s + qk + 1e-6f;
    }
    __syncthreads();
    {
        int oj = tid & 63;
        int ob = tid >> 6;
        int b = bh / H2, h = bh - b * H2;
        for (int r = 0; r < 32; r++) {
            int oi = ob + 4 * r;
            float acc = 0.f;
            const float* ar = As + oi * 129;
            for (int t = 0; t <= oi; t++) acc += ar[t] * Vs[t * DH + oj];
            const float* qr = Qs + oi * 65;
            #pragma unroll
            for (int d = 0; d < 64; d++) acc += qr[d] * Ss[d * DH + oj];
            int l = c * CHK + oi;
            attn_out[(size_t)(b * L2 + l) * D2 + h * DH + oj] = acc / Dn[oi];
        }
    }
}

// ---------------- launch ---------------------------------------------------
extern "C" void kernel_launch(void* const* d_in, const int* in_sizes, int n_in,
                              void* d_out, int out_size) {
    const float* x      = (const float*)d_in[0];
    const float* W_qkv  = (const float*)d_in[1];
    const float* b_qkv  = (const float*)d_in[2];
    const float* W_gate = (const float*)d_in[3];
    const float* b_gate = (const float*)d_in[4];
    const float* W_proj = (const float*)d_in[5];
    const float* b_proj = (const float*)d_in[6];
    const float* ln_g   = (const float*)d_in[7];
    const float* ln_b   = (const float*)d_in[8];
    float* out  = (float*)d_out;           // proj output
    float* gate = out + OUT_ELEMS;         // gate output (2nd return value)

    float *p_xn, *p_qkv, *p_qf, *p_kf, *p_vf, *p_kv, *p_ksum, *p_sprev, *p_ksp, *p_attn;
    float *p_wtq, *p_wtg, *p_wtp;
    cudaGetSymbolAddress((void**)&p_xn,    g_xn);
    cudaGetSymbolAddress((void**)&p_qkv,   g_qkv);
    cudaGetSymbolAddress((void**)&p_qf,    g_qf);
    cudaGetSymbolAddress((void**)&p_kf,    g_kf);
    cudaGetSymbolAddress((void**)&p_vf,    g_vf);
    cudaGetSymbolAddress((void**)&p_kv,    g_kv);
    cudaGetSymbolAddress((void**)&p_ksum,  g_ksum);
    cudaGetSymbolAddress((void**)&p_sprev, g_sprev);
    cudaGetSymbolAddress((void**)&p_ksp,   g_ksp);
    cudaGetSymbolAddress((void**)&p_attn,  g_attn);
    cudaGetSymbolAddress((void**)&p_wtq,   g_wt_qkv);
    cudaGetSymbolAddress((void**)&p_wtg,   g_wt_gate);
    cudaGetSymbolAddress((void**)&p_wtp,   g_wt_proj);

    cudaFuncSetAttribute(mma_gemm_kernel<0>, cudaFuncAttributeMaxDynamicSharedMemorySize,
                         GEMM_SMEM_BYTES);
    cudaFuncSetAttribute(mma_gemm_kernel<1>, cudaFuncAttributeMaxDynamicSharedMemorySize,
                         GEMM_SMEM_BYTES);
    cudaFuncSetAttribute(attn_kernel, cudaFuncAttributeMaxDynamicSharedMemorySize,
                         ATTN_SMEM_FLOATS * 4);

    // 0. transpose weights -> [N, K]
    transpose_kernel<<<dim3(N3D / 32, GK / 32), dim3(32, 8)>>>(W_qkv, p_wtq, GK, N3D);
    transpose_kernel<<<dim3(D2  / 32, GK / 32), dim3(32, 8)>>>(W_gate, p_wtg, GK, D2);
    transpose_kernel<<<dim3(D2  / 32, GK / 32), dim3(32, 8)>>>(W_proj, p_wtp, GK, D2);

    // 1. LayerNorm
    ln_kernel<<<BL, 256>>>(x, ln_g, ln_b, p_xn);

    // 2. qkv = xn @ W_qkv + b_qkv   (bf16x3 tensor cores)
    mma_gemm_kernel<0><<<dim3(N3D / 128, BL / 128), 256, GEMM_SMEM_BYTES>>>(
        p_xn, p_wtq, b_qkv, p_qkv, N3D);

    // 3. gate = sigmoid(x @ W_gate + b_gate)  (on raw x) -> second output
    mma_gemm_kernel<1><<<dim3(D2 / 128, BL / 128), 256, GEMM_SMEM_BYTES>>>(
        x, p_wtg, b_gate, gate, D2);

    // 4. split / gate-k / elu+1 / head layout
    prep_kernel<<<(BL * D2) / 256, 256>>>(p_qkv, gate, p_qf, p_kf, p_vf);

    // 5. per-chunk K^T V and ksum
    chunk_kv_kernel<<<dim3(NC, BH), 256>>>(p_kf, p_vf, p_kv, p_ksum);

    // 6. exclusive prefix over chunks
    scan_kernel<<<BH, 256>>>(p_kv, p_ksum, p_sprev, p_ksp);

    // 7. per-chunk attention
    attn_kernel<<<dim3(NC, BH), 256, ATTN_SMEM_FLOATS * 4>>>(
        p_qf, p_kf, p_vf, p_sprev, p_ksp, p_attn);

    // 8. out = attn @ W_proj + b_proj
    mma_gemm_kernel<0><<<dim3(D2 / 128, BL / 128), 256, GEMM_SMEM_BYTES>>>(
        p_attn, p_wtp, b_proj, out, D2);
}

// round 5
// speedup vs baseline: 1.9709x; 1.1349x over previous
#include <cuda_runtime.h>
#include <cuda_bf16.h>
#include <math.h>
#include <stdint.h>

// Problem constants
#define B2   2
#define L2   1024
#define D2   768
#define H2   12
#define DH   64
#define BH   (B2*H2)        // 24
#define BL   (B2*L2)        // 2048
#define N3D  (3*D2)         // 2304
#define CHK  128            // chunk length
#define NC   (L2/CHK)       // 8
#define GK   768            // shared K dim of all GEMMs
#define OUT_ELEMS (BL*D2)   // 1572864

typedef __nv_bfloat16 bf16;

// ---------------- scratch (device globals; no allocation allowed) ----------
__device__ float g_qkv[BL*N3D];
__device__ float g_qf[BH*L2*DH];
__device__ float g_kf[BH*L2*DH];
__device__ float g_vf[BH*L2*DH];
__device__ float g_kv[BH*NC*DH*DH];
__device__ float g_ksum[BH*NC*DH];
__device__ float g_sprev[BH*NC*DH*DH];
__device__ float g_ksp[BH*NC*DH];
// bf16 hi/lo pre-split operands (16B-aligned for cp.async)
__device__ __align__(256) bf16 g_ah[BL*GK];       // LN(x) hi
__device__ __align__(256) bf16 g_al[BL*GK];       // LN(x) lo
__device__ __align__(256) bf16 g_xh[BL*GK];       // raw x hi
__device__ __align__(256) bf16 g_xl[BL*GK];       // raw x lo
__device__ __align__(256) bf16 g_ath[BL*D2];      // attn out hi
__device__ __align__(256) bf16 g_atl[BL*D2];      // attn out lo
__device__ __align__(256) bf16 g_wtq_h[N3D*GK];
__device__ __align__(256) bf16 g_wtq_l[N3D*GK];
__device__ __align__(256) bf16 g_wtg_h[D2*GK];
__device__ __align__(256) bf16 g_wtg_l[D2*GK];
__device__ __align__(256) bf16 g_wtp_h[D2*GK];
__device__ __align__(256) bf16 g_wtp_l[D2*GK];

// =================== helpers ===============================================
__device__ __forceinline__ uint32_t smem_u32(const void* p) {
    uint32_t a;
    asm("{ .reg .u64 t; cvta.to.shared.u64 t, %1; cvt.u32.u64 %0, t; }"
        : "=r"(a) : "l"(p));
    return a;
}
__device__ __forceinline__ uint32_t sw128(uint32_t off) {
    return off ^ ((off >> 3) & 0x70);
}
__device__ __forceinline__ void split1(float v, bf16& h, bf16& l) {
    h = __float2bfloat16(v);
    l = __float2bfloat16(v - __bfloat162float(h));
}

#define LDSM4(r0, r1, r2, r3, addr) \
    asm volatile("ldmatrix.sync.aligned.m8n8.x4.shared.b16 {%0,%1,%2,%3}, [%4];" \
        : "=r"(r0), "=r"(r1), "=r"(r2), "=r"(r3) : "r"(addr))

#define MMA_BF16(d, a, b) \
    asm volatile("mma.sync.aligned.m16n8k16.row.col.f32.bf16.bf16.f32 " \
        "{%0,%1,%2,%3},{%4,%5,%6,%7},{%8,%9},{%0,%1,%2,%3};" \
        : "+f"((d)[0]), "+f"((d)[1]), "+f"((d)[2]), "+f"((d)[3]) \
        : "r"((a)[0]), "r"((a)[1]), "r"((a)[2]), "r"((a)[3]), \
          "r"((b)[0]), "r"((b)[1]))

#define CP_ASYNC16(dst, src) \
    asm volatile("cp.async.cg.shared.global [%0], [%1], 16;" \
        :: "r"((uint32_t)(dst)), "l"(src))
#define CP_COMMIT() asm volatile("cp.async.commit_group;" ::: "memory")
#define CP_WAIT(n)  asm volatile("cp.async.wait_group %0;" :: "n"(n) : "memory")

// ---------------- LayerNorm + bf16 hi/lo split -----------------------------
__global__ void ln_kernel(const float* __restrict__ x,
                          const float* __restrict__ g,
                          const float* __restrict__ b,
                          bf16* __restrict__ xh, bf16* __restrict__ xl) {
    int row = blockIdx.x;
    int tid = threadIdx.x;  // 256
    const float* xr = x + row * D2;
    float v0 = xr[tid], v1 = xr[tid + 256], v2 = xr[tid + 512];
    float s  = v0 + v1 + v2;
    float sq = v0*v0 + v1*v1 + v2*v2;
    #pragma unroll
    for (int o = 16; o; o >>= 1) {
        s  += __shfl_xor_sync(0xffffffffu, s,  o);
        sq += __shfl_xor_sync(0xffffffffu, sq, o);
    }
    __shared__ float ss[8], sqs[8];
    if ((tid & 31) == 0) { ss[tid >> 5] = s; sqs[tid >> 5] = sq; }
    __syncthreads();
    float ts = 0.f, tq = 0.f;
    #pragma unroll
    for (int w = 0; w < 8; w++) { ts += ss[w]; tq += sqs[w]; }
    float mean = ts * (1.f / D2);
    float var  = tq * (1.f / D2) - mean * mean;
    float inv  = rsqrtf(var + 1e-5f);
    bf16 *hh = xh + (size_t)row * D2, *ll = xl + (size_t)row * D2;
    #pragma unroll
    for (int p = 0; p < 3; p++) {
        int cc = tid + 256 * p;
        float v = (p == 0 ? v0 : (p == 1 ? v1 : v2));
        float xnv = (v - mean) * inv * g[cc] + b[cc];
        bf16 h, l; split1(xnv, h, l);
        hh[cc] = h; ll[cc] = l;
    }
}

// ---------------- raw-x bf16 split -----------------------------------------
__global__ void xsplit_kernel(const float* __restrict__ x,
                              bf16* __restrict__ xh, bf16* __restrict__ xl) {
    int i = blockIdx.x * 256 + threadIdx.x;
    bf16 h, l; split1(x[i], h, l);
    xh[i] = h; xl[i] = l;
}

// ---------------- W[K,N] -> Wt[N,K] transpose + split ----------------------
__global__ void transpose_kernel(const float* __restrict__ W,
                                 bf16* __restrict__ WtH, bf16* __restrict__ WtL,
                                 int K, int N) {
    __shared__ float t[32][33];
    int n0 = blockIdx.x * 32, k0 = blockIdx.y * 32;
    int tx = threadIdx.x, ty = threadIdx.y;   // (32, 8)
    #pragma unroll
    for (int r = ty; r < 32; r += 8)
        t[r][tx] = W[(size_t)(k0 + r) * N + n0 + tx];
    __syncthreads();
    #pragma unroll
    for (int r = ty; r < 32; r += 8) {
        bf16 h, l; split1(t[tx][r], h, l);
        WtH[(size_t)(n0 + r) * K + k0 + tx] = h;
        WtL[(size_t)(n0 + r) * K + k0 + tx] = l;
    }
}

// ---------------- bf16x3 mma.sync GEMM with cp.async pipeline --------------
// C[M,N] = A[M,768] @ Wt[N,768]^T + bias. BM=BN=128, BK=64, 2-stage cp.async.
// SMEM stage (65536 B): Ah 16K | Al 16K | Bh 16K | Bl 16K. Rows = 128B, SW128.
#define BKC 64
#define STG_A_HI 0
#define STG_A_LO 16384
#define STG_B_HI 32768
#define STG_B_LO 49152
#define GEMM_STAGE_BYTES 65536
#define GEMM_SMEM_BYTES  (2 * GEMM_STAGE_BYTES)
#define NCHUNK (GK / BKC)   // 12

template <int EPI>   // 0 = none, 1 = sigmoid
__global__ void __launch_bounds__(256, 1) mma_gemm_kernel(
    const bf16* __restrict__ AHp, const bf16* __restrict__ ALp,
    const bf16* __restrict__ WHp, const bf16* __restrict__ WLp,
    const float* __restrict__ bias,
    float* __restrict__ C, int Nld)
{
    extern __shared__ char smem[];
    uint32_t sb = smem_u32(smem);
    int tid  = threadIdx.x;
    int wid  = tid >> 5, lane = tid & 31;
    int wm   = wid >> 2, wn = wid & 3;        // warp grid 2x4
    int m0   = wm * 64;                       // warp tile 64x32
    int n0   = wn * 32;
    int lr   = lane & 7, g = lane >> 3;
    int arow = ((g & 1) << 3) + lr;
    int acolb = (g >> 1) << 4;
    int brow = ((g >> 1) << 3) + lr;
    int bcolb = (g & 1) << 4;

    const bf16* ApH = AHp + (size_t)blockIdx.y * 128 * GK;
    const bf16* ApL = ALp + (size_t)blockIdx.y * 128 * GK;
    const bf16* BpH = WHp + (size_t)blockIdx.x * 128 * GK;
    const bf16* BpL = WLp + (size_t)blockIdx.x * 128 * GK;

    // per-thread cp.async positions: 1024 16B segments per array, 4 per thread
    int srow[4], sseg[4]; uint32_t soff[4];
    #pragma unroll
    for (int i = 0; i < 4; i++) {
        int idx = tid + 256 * i;
        srow[i] = idx >> 3;
        sseg[i] = idx & 7;
        soff[i] = sw128((uint32_t)(srow[i] * 128 + sseg[i] * 16));
    }

    float acc[4][4][4];
    #pragma unroll
    for (int mt = 0; mt < 4; mt++)
        #pragma unroll
        for (int nt = 0; nt < 4; nt++)
            #pragma unroll
            for (int q = 0; q < 4; q++) acc[mt][nt][q] = 0.f;

    // prologue: issue chunk 0 into stage 0
    {
        uint32_t db = sb;
        #pragma unroll
        for (int i = 0; i < 4; i++) {
            size_t off = (size_t)srow[i] * GK + sseg[i] * 8;
            CP_ASYNC16(db + STG_A_HI + soff[i], ApH + off);
            CP_ASYNC16(db + STG_A_LO + soff[i], ApL + off);
            CP_ASYNC16(db + STG_B_HI + soff[i], BpH + off);
            CP_ASYNC16(db + STG_B_LO + soff[i], BpL + off);
        }
        CP_COMMIT();
    }

    for (int c = 0; c < NCHUNK; c++) {
        int stage = c & 1;
        if (c + 1 < NCHUNK) {
            uint32_t db = sb + (stage ^ 1) * GEMM_STAGE_BYTES;
            int k0 = (c + 1) * BKC;
            #pragma unroll
            for (int i = 0; i < 4; i++) {
                size_t off = (size_t)srow[i] * GK + k0 + sseg[i] * 8;
                CP_ASYNC16(db + STG_A_HI + soff[i], ApH + off);
                CP_ASYNC16(db + STG_A_LO + soff[i], ApL + off);
                CP_ASYNC16(db + STG_B_HI + soff[i], BpH + off);
                CP_ASYNC16(db + STG_B_LO + soff[i], BpL + off);
            }
            CP_COMMIT();
            CP_WAIT(1);
        } else {
            CP_WAIT(0);
        }
        __syncthreads();

        uint32_t sA  = sb + stage * GEMM_STAGE_BYTES;
        uint32_t sAl = sA + STG_A_LO;
        uint32_t sBh = sA + STG_B_HI;
        uint32_t sBl = sA + STG_B_LO;
        #pragma unroll
        for (int kt = 0; kt < 4; kt++) {
            uint32_t bh[4][2], bl[4][2];
            #pragma unroll
            for (int t = 0; t < 2; t++) {
                uint32_t boff = sw128((uint32_t)((n0 + t * 16 + brow) * 128 + kt * 32 + bcolb));
                LDSM4(bh[2*t][0], bh[2*t][1], bh[2*t+1][0], bh[2*t+1][1], sBh + boff);
                LDSM4(bl[2*t][0], bl[2*t][1], bl[2*t+1][0], bl[2*t+1][1], sBl + boff);
            }
            #pragma unroll
            for (int mt = 0; mt < 4; mt++) {
                uint32_t aoff = sw128((uint32_t)((m0 + mt * 16 + arow) * 128 + kt * 32 + acolb));
                uint32_t ah[4], al[4];
                LDSM4(ah[0], ah[1], ah[2], ah[3], sA  + aoff);
                LDSM4(al[0], al[1], al[2], al[3], sAl + aoff);
                #pragma unroll
                for (int nt = 0; nt < 4; nt++) {
                    MMA_BF16(acc[mt][nt], ah, bh[nt]);
                    MMA_BF16(acc[mt][nt], ah, bl[nt]);
                    MMA_BF16(acc[mt][nt], al, bh[nt]);
                }
            }
        }
        __syncthreads();
    }

    // epilogue
    int rbase = blockIdx.y * 128 + m0 + (lane >> 2);
    int cbase = blockIdx.x * 128 + n0 + ((lane & 3) << 1);
    #pragma unroll
    for (int mt = 0; mt < 4; mt++) {
        #pragma unroll
        for (int nt = 0; nt < 4; nt++) {
            int col = cbase + nt * 8;
            float b0 = bias[col], b1 = bias[col + 1];
            #pragma unroll
            for (int h = 0; h < 2; h++) {
                int row = rbase + mt * 16 + h * 8;
                float o0 = acc[mt][nt][2*h + 0] + b0;
                float o1 = acc[mt][nt][2*h + 1] + b1;
                if (EPI == 1) {
                    o0 = 1.f / (1.f + expf(-o0));
                    o1 = 1.f / (1.f + expf(-o1));
                }
                *(float2*)(C + (size_t)row * Nld + col) = make_float2(o0, o1);
            }
        }
    }
}

// ---------------- prep: split qkv, apply gate to k, elu+1, head layout ----
__global__ void prep_kernel(const float* __restrict__ qkv,
                            const float* __restrict__ gate,
                            float* __restrict__ qf,
                            float* __restrict__ kf,
                            float* __restrict__ vf) {
    int idx = blockIdx.x * 256 + threadIdx.x;     // 0 .. BL*D2
    int bl = idx / D2;
    int c  = idx - bl * D2;
    int h = c >> 6, d = c & 63;
    int b = bl >> 10, l = bl & 1023;
    float q = qkv[(size_t)bl * N3D + c];
    float k = qkv[(size_t)bl * N3D + D2 + c] * gate[idx];
    float v = qkv[(size_t)bl * N3D + 2 * D2 + c];
    int o = ((b * H2 + h) * L2 + l) * DH + d;
    qf[o] = (q > 0.f) ? (q + 1.f) : expf(q);
    kf[o] = (k > 0.f) ? (k + 1.f) : expf(k);
    vf[o] = v;
}

// ---------------- per-chunk K^T V (64x64) and ksum (64) -------------------
__global__ void chunk_kv_kernel(const float* __restrict__ kf,
                                const float* __restrict__ vf,
                                float* __restrict__ kv,
                                float* __restrict__ ksum) {
    __shared__ float Ks[32][64];
    __shared__ float Vs[32][64];
    int c = blockIdx.x, bh = blockIdx.y;
    int tid = threadIdx.x;   // 256
    const float* kp = kf + (size_t)(bh * L2 + c * CHK) * DH;
    const float* vp = vf + (size_t)(bh * L2 + c * CHK) * DH;
    int j = tid & 63;
    int ibase = tid >> 6;    // 0..3
    float acc[16];
    #pragma unroll
    for (int r = 0; r < 16; r++) acc[r] = 0.f;
    float ks = 0.f;
    for (int tt = 0; tt < 4; tt++) {
        for (int i = tid; i < 512; i += 256) {
            int row = i >> 4, col = (i & 15) << 2;
            *(float4*)&Ks[row][col] = *(const float4*)(kp + (size_t)(tt*32 + row)*DH + col);
            *(float4*)&Vs[row][col] = *(const float4*)(vp + (size_t)(tt*32 + row)*DH + col);
        }
        __syncthreads();
        #pragma unroll 4
        for (int t = 0; t < 32; t++) {
            float vj = Vs[t][j];
            #pragma unroll
            for (int r = 0; r < 16; r++)
                acc[r] += Ks[t][ibase + 4 * r] * vj;
        }
        if (tid < 64) {
            #pragma unroll 4
            for (int t = 0; t < 32; t++) ks += Ks[t][tid];
        }
        __syncthreads();
    }
    float* kvp = kv + (size_t)(bh * NC + c) * DH * DH;
    #pragma unroll
    for (int r = 0; r < 16; r++)
        kvp[(ibase + 4 * r) * DH + j] = acc[r];
    if (tid < 64) ksum[(bh * NC + c) * DH + tid] = ks;
}

// ---------------- exclusive prefix over chunks ----------------------------
__global__ void scan_kernel(const float* __restrict__ kv,
                            const float* __restrict__ ksum,
                            float* __restrict__ sprev,
                            float* __restrict__ ksp) {
    int bh = blockIdx.x;
    int tid = threadIdx.x;  // 256
    #pragma unroll
    for (int r = 0; r < 16; r++) {
        int e = tid + 256 * r;
        float acc = 0.f;
        #pragma unroll
        for (int c = 0; c < NC; c++) {
            size_t o = (size_t)(bh * NC + c) * DH * DH + e;
            sprev[o] = acc;
            acc += kv[o];
        }
    }
    if (tid < 64) {
        float acc = 0.f;
        #pragma unroll
        for (int c = 0; c < NC; c++) {
            size_t o = (size_t)(bh * NC + c) * DH + tid;
            ksp[o] = acc;
            acc += ksum[o];
        }
    }
}

// ---------------- per-chunk attention output ------------------------------
#define SM_Q   0
#define SM_K   (128*65)
#define SM_V   (SM_K + 128*65)
#define SM_A   (SM_V + 128*64)
#define SM_S   (SM_A + 128*129)
#define SM_KS  (SM_S + 64*64)
#define SM_DEN (SM_KS + 64)
#define ATTN_SMEM_FLOATS (SM_DEN + 128)

__global__ void attn_kernel(const float* __restrict__ qf,
                            const float* __restrict__ kf,
                            const float* __restrict__ vf,
                            const float* __restrict__ sprev,
                            const float* __restrict__ ksp,
                            bf16* __restrict__ aoh,
                            bf16* __restrict__ aol) {
    extern __shared__ float sm[];
    float* Qs = sm + SM_Q;
    float* Ks = sm + SM_K;
    float* Vs = sm + SM_V;
    float* As = sm + SM_A;
    float* Ss = sm + SM_S;
    float* Kp = sm + SM_KS;
    float* Dn = sm + SM_DEN;
    int c = blockIdx.x, bh = blockIdx.y;
    int tid = threadIdx.x;   // 256
    const float* qp = qf + (size_t)(bh * L2 + c * CHK) * DH;
    const float* kp = kf + (size_t)(bh * L2 + c * CHK) * DH;
    const float* vp = vf + (size_t)(bh * L2 + c * CHK) * DH;
    for (int i = tid; i < 2048; i += 256) {
        int row = i >> 4, col = (i & 15) << 2;
        float4 q4 = *(const float4*)(qp + (size_t)row * DH + col);
        float4 k4 = *(const float4*)(kp + (size_t)row * DH + col);
        float* qd = Qs + row * 65 + col;
        float* kd = Ks + row * 65 + col;
        qd[0]=q4.x; qd[1]=q4.y; qd[2]=q4.z; qd[3]=q4.w;
        kd[0]=k4.x; kd[1]=k4.y; kd[2]=k4.z; kd[3]=k4.w;
        *(float4*)(Vs + row * DH + col) = *(const float4*)(vp + (size_t)row * DH + col);
    }
    {
        const float4* sp = (const float4*)(sprev + (size_t)(bh * NC + c) * DH * DH);
        for (int i = tid; i < 1024; i += 256) ((float4*)Ss)[i] = sp[i];
        if (tid < 16)
            ((float4*)Kp)[tid] = ((const float4*)(ksp + (size_t)(bh * NC + c) * DH))[tid];
    }
    __syncthreads();
    {
        int aj = tid & 127;
        int ib = tid >> 7;
        for (int r = 0; r < 64; r++) {
            int ai = ib + 2 * r;
            float acc = 0.f;
            if (aj <= ai) {
                const float* qr = Qs + ai * 65;
                const float* kr = Ks + aj * 65;
                #pragma unroll
                for (int d = 0; d < 64; d++) acc += qr[d] * kr[d];
            }
            As[ai * 129 + aj] = acc;
        }
    }
    __syncthreads();
    if (tid < 128) {
        float s = 0.f;
        const float* ar = As + tid * 129;
        for (int j = 0; j <= tid; j++) s += ar[j];
        const float* qr = Qs + tid * 65;
        float qk = 0.f;
        #pragma unroll
        for (int d = 0; d < 64; d++) qk += qr[d] * Kp[d];
        Dn[tid] = s + qk + 1e-6f;
    }
    __syncthreads();
    {
        int oj = tid & 63;
        int ob = tid >> 6;
        int b = bh / H2, h = bh - b * H2;
        for (int r = 0; r < 32; r++) {
            int oi = ob + 4 * r;
            float acc = 0.f;
            const float* ar = As + oi * 129;
            for (int t = 0; t <= oi; t++) acc += ar[t] * Vs[t * DH + oj];
            const float* qr = Qs + oi * 65;
            #pragma unroll
            for (int d = 0; d < 64; d++) acc += qr[d] * Ss[d * DH + oj];
            int l = c * CHK + oi;
            float val = acc / Dn[oi];
            bf16 hv, lv; split1(val, hv, lv);
            size_t o = (size_t)(b * L2 + l) * D2 + h * DH + oj;
            aoh[o] = hv; aol[o] = lv;
        }
    }
}

// ---------------- launch ---------------------------------------------------
extern "C" void kernel_launch(void* const* d_in, const int* in_sizes, int n_in,
                              void* d_out, int out_size) {
    const float* x      = (const float*)d_in[0];
    const float* W_qkv  = (const float*)d_in[1];
    const float* b_qkv  = (const float*)d_in[2];
    const float* W_gate = (const float*)d_in[3];
    const float* b_gate = (const float*)d_in[4];
    const float* W_proj = (const float*)d_in[5];
    const float* b_proj = (const float*)d_in[6];
    const float* ln_g   = (const float*)d_in[7];
    const float* ln_b   = (const float*)d_in[8];
    float* out  = (float*)d_out;           // proj output
    float* gate = out + OUT_ELEMS;         // gate output (2nd return value)

    float *p_qkv, *p_qf, *p_kf, *p_vf, *p_kv, *p_ksum, *p_sprev, *p_ksp;
    bf16 *p_ah, *p_al, *p_xh, *p_xl, *p_ath, *p_atl;
    bf16 *p_wtq_h, *p_wtq_l, *p_wtg_h, *p_wtg_l, *p_wtp_h, *p_wtp_l;
    cudaGetSymbolAddress((void**)&p_qkv,   g_qkv);
    cudaGetSymbolAddress((void**)&p_qf,    g_qf);
    cudaGetSymbolAddress((void**)&p_kf,    g_kf);
    cudaGetSymbolAddress((void**)&p_vf,    g_vf);
    cudaGetSymbolAddress((void**)&p_kv,    g_kv);
    cudaGetSymbolAddress((void**)&p_ksum,  g_ksum);
    cudaGetSymbolAddress((void**)&p_sprev, g_sprev);
    cudaGetSymbolAddress((void**)&p_ksp,   g_ksp);
    cudaGetSymbolAddress((void**)&p_ah,    g_ah);
    cudaGetSymbolAddress((void**)&p_al,    g_al);
    cudaGetSymbolAddress((void**)&p_xh,    g_xh);
    cudaGetSymbolAddress((void**)&p_xl,    g_xl);
    cudaGetSymbolAddress((void**)&p_ath,   g_ath);
    cudaGetSymbolAddress((void**)&p_atl,   g_atl);
    cudaGetSymbolAddress((void**)&p_wtq_h, g_wtq_h);
    cudaGetSymbolAddress((void**)&p_wtq_l, g_wtq_l);
    cudaGetSymbolAddress((void**)&p_wtg_h, g_wtg_h);
    cudaGetSymbolAddress((void**)&p_wtg_l, g_wtg_l);
    cudaGetSymbolAddress((void**)&p_wtp_h, g_wtp_h);
    cudaGetSymbolAddress((void**)&p_wtp_l, g_wtp_l);

    cudaFuncSetAttribute(mma_gemm_kernel<0>, cudaFuncAttributeMaxDynamicSharedMemorySize,
                         GEMM_SMEM_BYTES);
    cudaFuncSetAttribute(mma_gemm_kernel<1>, cudaFuncAttributeMaxDynamicSharedMemorySize,
                         GEMM_SMEM_BYTES);
    cudaFuncSetAttribute(attn_kernel, cudaFuncAttributeMaxDynamicSharedMemorySize,
                         ATTN_SMEM_FLOATS * 4);

    // 0. transpose + split weights -> [N, K] bf16 hi/lo
    transpose_kernel<<<dim3(N3D / 32, GK / 32), dim3(32, 8)>>>(W_qkv, p_wtq_h, p_wtq_l, GK, N3D);
    transpose_kernel<<<dim3(D2  / 32, GK / 32), dim3(32, 8)>>>(W_gate, p_wtg_h, p_wtg_l, GK, D2);
    transpose_kernel<<<dim3(D2  / 32, GK / 32), dim3(32, 8)>>>(W_proj, p_wtp_h, p_wtp_l, GK, D2);

    // 1. LayerNorm (fused split) + raw-x split
    ln_kernel<<<BL, 256>>>(x, ln_g, ln_b, p_ah, p_al);
    xsplit_kernel<<<(BL * D2) / 256, 256>>>(x, p_xh, p_xl);

    // 2. qkv = xn @ W_qkv + b_qkv   (bf16x3 tensor cores)
    mma_gemm_kernel<0><<<dim3(N3D / 128, BL / 128), 256, GEMM_SMEM_BYTES>>>(
        p_ah, p_al, p_wtq_h, p_wtq_l, b_qkv, p_qkv, N3D);

    // 3. gate = sigmoid(x @ W_gate + b_gate)  (on raw x) -> second output
    mma_gemm_kernel<1><<<dim3(D2 / 128, BL / 128), 256, GEMM_SMEM_BYTES>>>(
        p_xh, p_xl, p_wtg_h, p_wtg_l, b_gate, gate, D2);

    // 4. split / gate-k / elu+1 / head layout
    prep_kernel<<<(BL * D2) / 256, 256>>>(p_qkv, gate, p_qf, p_kf, p_vf);

    // 5. per-chunk K^T V and ksum
    chunk_kv_kernel<<<dim3(NC, BH), 256>>>(p_kf, p_vf, p_kv, p_ksum);

    // 6. exclusive prefix over chunks
    scan_kernel<<<BH, 256>>>(p_kv, p_ksum, p_sprev, p_ksp);

    // 7. per-chunk attention (fused bf16 split of output)
    attn_kernel<<<dim3(NC, BH), 256, ATTN_SMEM_FLOATS * 4>>>(
        p_qf, p_kf, p_vf, p_sprev, p_ksp, p_ath, p_atl);

    // 8. out = attn @ W_proj + b_proj
    mma_gemm_kernel<0><<<dim3(D2 / 128, BL / 128), 256, GEMM_SMEM_BYTES>>>(
        p_ath, p_atl, p_wtp_h, p_wtp_l, b_proj, out, D2);
}

// round 6
// speedup vs baseline: 2.2841x; 1.1589x over previous
#include <cuda_runtime.h>
#include <cuda_fp16.h>
#include <math.h>
#include <stdint.h>

// Problem constants
#define B2   2
#define L2   1024
#define D2   768
#define H2   12
#define DH   64
#define BH   (B2*H2)        // 24
#define BL   (B2*L2)        // 2048
#define N3D  (3*D2)         // 2304
#define CHK  128            // chunk length
#define NC   (L2/CHK)       // 8
#define GK   768            // shared K dim of all GEMMs
#define OUT_ELEMS (BL*D2)   // 1572864

// ---------------- scratch (device globals; no allocation allowed) ----------
__device__ float g_qkv[BL*N3D];
__device__ float g_qf[BH*L2*DH];
__device__ float g_kf[BH*L2*DH];
__device__ float g_vf[BH*L2*DH];
__device__ float g_kv[BH*NC*DH*DH];
__device__ float g_ksum[BH*NC*DH];
__device__ float g_sprev[BH*NC*DH*DH];
__device__ float g_ksp[BH*NC*DH];
// fp16 pre-split operands (16B-aligned for cp.async)
__device__ __align__(256) __half g_ah[BL*GK];       // LN(x) hi
__device__ __align__(256) __half g_al[BL*GK];       // LN(x) lo
__device__ __align__(256) __half g_xh[BL*GK];       // raw x hi
__device__ __align__(256) __half g_xl[BL*GK];       // raw x lo
__device__ __align__(256) __half g_ath[BL*D2];      // attn out hi
__device__ __align__(256) __half g_atl[BL*D2];      // attn out lo
__device__ __align__(256) __half g_wtq[N3D*GK];     // W_qkv^T fp16
__device__ __align__(256) __half g_wtg[D2*GK];      // W_gate^T fp16
__device__ __align__(256) __half g_wtp[D2*GK];      // W_proj^T fp16

// =================== helpers ===============================================
__device__ __forceinline__ uint32_t smem_u32(const void* p) {
    uint32_t a;
    asm("{ .reg .u64 t; cvta.to.shared.u64 t, %1; cvt.u32.u64 %0, t; }"
        : "=r"(a) : "l"(p));
    return a;
}
__device__ __forceinline__ uint32_t sw128(uint32_t off) {
    return off ^ ((off >> 3) & 0x70);
}
__device__ __forceinline__ void split1h(float v, __half& h, __half& l) {
    h = __float2half_rn(v);
    l = __float2half_rn(v - __half2float(h));
}

#define LDSM4(r0, r1, r2, r3, addr) \
    asm volatile("ldmatrix.sync.aligned.m8n8.x4.shared.b16 {%0,%1,%2,%3}, [%4];" \
        : "=r"(r0), "=r"(r1), "=r"(r2), "=r"(r3) : "r"(addr))

#define MMA_F16(d, a, b) \
    asm volatile("mma.sync.aligned.m16n8k16.row.col.f32.f16.f16.f32 " \
        "{%0,%1,%2,%3},{%4,%5,%6,%7},{%8,%9},{%0,%1,%2,%3};" \
        : "+f"((d)[0]), "+f"((d)[1]), "+f"((d)[2]), "+f"((d)[3]) \
        : "r"((a)[0]), "r"((a)[1]), "r"((a)[2]), "r"((a)[3]), \
          "r"((b)[0]), "r"((b)[1]))

#define CP_ASYNC16(dst, src) \
    asm volatile("cp.async.cg.shared.global [%0], [%1], 16;" \
        :: "r"((uint32_t)(dst)), "l"(src))
#define CP_COMMIT() asm volatile("cp.async.commit_group;" ::: "memory")
#define CP_WAIT(n)  asm volatile("cp.async.wait_group %0;" :: "n"(n) : "memory")

// ---------------- LayerNorm + fp16 hi/lo split -----------------------------
__global__ void ln_kernel(const float* __restrict__ x,
                          const float* __restrict__ g,
                          const float* __restrict__ b,
                          __half* __restrict__ xh, __half* __restrict__ xl) {
    int row = blockIdx.x;
    int tid = threadIdx.x;  // 256
    const float* xr = x + row * D2;
    float v0 = xr[tid], v1 = xr[tid + 256], v2 = xr[tid + 512];
    float s  = v0 + v1 + v2;
    float sq = v0*v0 + v1*v1 + v2*v2;
    #pragma unroll
    for (int o = 16; o; o >>= 1) {
        s  += __shfl_xor_sync(0xffffffffu, s,  o);
        sq += __shfl_xor_sync(0xffffffffu, sq, o);
    }
    __shared__ float ss[8], sqs[8];
    if ((tid & 31) == 0) { ss[tid >> 5] = s; sqs[tid >> 5] = sq; }
    __syncthreads();
    float ts = 0.f, tq = 0.f;
    #pragma unroll
    for (int w = 0; w < 8; w++) { ts += ss[w]; tq += sqs[w]; }
    float mean = ts * (1.f / D2);
    float var  = tq * (1.f / D2) - mean * mean;
    float inv  = rsqrtf(var + 1e-5f);
    __half *hh = xh + (size_t)row * D2, *ll = xl + (size_t)row * D2;
    #pragma unroll
    for (int p = 0; p < 3; p++) {
        int cc = tid + 256 * p;
        float v = (p == 0 ? v0 : (p == 1 ? v1 : v2));
        float xnv = (v - mean) * inv * g[cc] + b[cc];
        __half h, l; split1h(xnv, h, l);
        hh[cc] = h; ll[cc] = l;
    }
}

// ---------------- raw-x fp16 split -----------------------------------------
__global__ void xsplit_kernel(const float* __restrict__ x,
                              __half* __restrict__ xh, __half* __restrict__ xl) {
    int i = blockIdx.x * 256 + threadIdx.x;
    __half h, l; split1h(x[i], h, l);
    xh[i] = h; xl[i] = l;
}

// ---------------- W[K,N] -> Wt[N,K] transpose to fp16 ----------------------
__global__ void transpose_kernel(const float* __restrict__ W,
                                 __half* __restrict__ Wt, int K, int N) {
    __shared__ float t[32][33];
    int n0 = blockIdx.x * 32, k0 = blockIdx.y * 32;
    int tx = threadIdx.x, ty = threadIdx.y;   // (32, 8)
    #pragma unroll
    for (int r = ty; r < 32; r += 8)
        t[r][tx] = W[(size_t)(k0 + r) * N + n0 + tx];
    __syncthreads();
    #pragma unroll
    for (int r = ty; r < 32; r += 8)
        Wt[(size_t)(n0 + r) * K + k0 + tx] = __float2half_rn(t[tx][r]);
}

// ---------------- fp16x2 mma.sync GEMM, 3-stage cp.async ring --------------
// C[M,N] = (Ah+Al)[M,768] @ Wt[N,768]^T + bias.
// BM=BN=128, BK=64. Stage (49152 B): Ah 16K | Al 16K | B 16K. SW128 rows=128B.
#define BKC 64
#define STG_AH 0
#define STG_AL 16384
#define STG_B  32768
#define STAGE_B 49152
#define NSTG 3
#define GEMM_SMEM_BYTES (NSTG * STAGE_B)   // 147456
#define NCHUNK (GK / BKC)   // 12

__device__ __forceinline__ void gemm_core(char* smem,
    const __half* __restrict__ ApH, const __half* __restrict__ ApL,
    const __half* __restrict__ Bp,
    const float* __restrict__ bias, float* __restrict__ C,
    int Nld, int cb0, int rb0, int sig)
{
    uint32_t sb = smem_u32(smem);
    int tid  = threadIdx.x;
    int wid  = tid >> 5, lane = tid & 31;
    int wm   = wid >> 2, wn = wid & 3;        // warp grid 2x4
    int m0   = wm * 64;                       // warp tile 64x32
    int n0   = wn * 32;
    int lr   = lane & 7, g = lane >> 3;
    int arow = ((g & 1) << 3) + lr;
    int acolb = (g >> 1) << 4;
    int brow = ((g >> 1) << 3) + lr;
    int bcolb = (g & 1) << 4;

    // per-thread cp.async positions: 1024 16B segments per array, 4 per thread
    int srow[4], sseg[4]; uint32_t soff[4];
    #pragma unroll
    for (int i = 0; i < 4; i++) {
        int idx = tid + 256 * i;
        srow[i] = idx >> 3;
        sseg[i] = idx & 7;
        soff[i] = sw128((uint32_t)(srow[i] * 128 + sseg[i] * 16));
    }

    float acc[4][4][4];
    #pragma unroll
    for (int mt = 0; mt < 4; mt++)
        #pragma unroll
        for (int nt = 0; nt < 4; nt++)
            #pragma unroll
            for (int q = 0; q < 4; q++) acc[mt][nt][q] = 0.f;

    // prologue: issue chunks 0 .. NSTG-2
    #pragma unroll
    for (int p = 0; p < NSTG - 1; p++) {
        uint32_t db = sb + p * STAGE_B;
        #pragma unroll
        for (int i = 0; i < 4; i++) {
            size_t off = (size_t)srow[i] * GK + p * BKC + sseg[i] * 8;
            CP_ASYNC16(db + STG_AH + soff[i], ApH + off);
            CP_ASYNC16(db + STG_AL + soff[i], ApL + off);
            CP_ASYNC16(db + STG_B  + soff[i], Bp  + off);
        }
        CP_COMMIT();
    }

    int st = 0, wst = NSTG - 1;
    for (int c = 0; c < NCHUNK; c++) {
        CP_WAIT(NSTG - 2);
        __syncthreads();
        if (c + NSTG - 1 < NCHUNK) {
            uint32_t db = sb + wst * STAGE_B;
            int k0 = (c + NSTG - 1) * BKC;
            #pragma unroll
            for (int i = 0; i < 4; i++) {
                size_t off = (size_t)srow[i] * GK + k0 + sseg[i] * 8;
                CP_ASYNC16(db + STG_AH + soff[i], ApH + off);
                CP_ASYNC16(db + STG_AL + soff[i], ApL + off);
                CP_ASYNC16(db + STG_B  + soff[i], Bp  + off);
            }
        }
        CP_COMMIT();   // empty group near the tail keeps WAIT semantics correct

        uint32_t sA  = sb + st * STAGE_B;
        uint32_t sAl = sA + STG_AL;
        uint32_t sB  = sA + STG_B;
        #pragma unroll
        for (int kt = 0; kt < 4; kt++) {
            uint32_t bf[4][2];
            #pragma unroll
            for (int t = 0; t < 2; t++) {
                uint32_t boff = sw128((uint32_t)((n0 + t * 16 + brow) * 128 + kt * 32 + bcolb));
                LDSM4(bf[2*t][0], bf[2*t][1], bf[2*t+1][0], bf[2*t+1][1], sB + boff);
            }
            #pragma unroll
            for (int mt = 0; mt < 4; mt++) {
                uint32_t aoff = sw128((uint32_t)((m0 + mt * 16 + arow) * 128 + kt * 32 + acolb));
                uint32_t ah[4], al[4];
                LDSM4(ah[0], ah[1], ah[2], ah[3], sA  + aoff);
                LDSM4(al[0], al[1], al[2], al[3], sAl + aoff);
                #pragma unroll
                for (int nt = 0; nt < 4; nt++) {
                    MMA_F16(acc[mt][nt], ah, bf[nt]);
                    MMA_F16(acc[mt][nt], al, bf[nt]);
                }
            }
        }
        st  = (st  + 1 == NSTG) ? 0 : st  + 1;
        wst = (wst + 1 == NSTG) ? 0 : wst + 1;
    }

    // epilogue
    int rbase = rb0 + m0 + (lane >> 2);
    int cbase = cb0 + n0 + ((lane & 3) << 1);
    #pragma unroll
    for (int mt = 0; mt < 4; mt++) {
        #pragma unroll
        for (int nt = 0; nt < 4; nt++) {
            int col = cbase + nt * 8;
            float b0 = bias[col], b1 = bias[col + 1];
            #pragma unroll
            for (int h = 0; h < 2; h++) {
                int row = rbase + mt * 16 + h * 8;
                float o0 = acc[mt][nt][2*h + 0] + b0;
                float o1 = acc[mt][nt][2*h + 1] + b1;
                if (sig) {
                    o0 = 1.f / (1.f + expf(-o0));
                    o1 = 1.f / (1.f + expf(-o1));
                }
                *(float2*)(C + (size_t)row * Nld + col) = make_float2(o0, o1);
            }
        }
    }
}

// fused QKV + gate GEMM: bx<18 -> QKV tile, bx>=18 -> gate tile (sigmoid)
__global__ void __launch_bounds__(256, 1) gemm_qkv_gate(
    const __half* __restrict__ xnh, const __half* __restrict__ xnl,
    const __half* __restrict__ wq,  const float* __restrict__ bq,
    float* __restrict__ qkvC,
    const __half* __restrict__ xh,  const __half* __restrict__ xl,
    const __half* __restrict__ wg,  const float* __restrict__ bg,
    float* __restrict__ gateC)
{
    extern __shared__ char smem[];
    int bx = blockIdx.x, by = blockIdx.y;
    if (bx < N3D / 128) {
        gemm_core(smem, xnh + (size_t)by * 128 * GK, xnl + (size_t)by * 128 * GK,
                  wq + (size_t)bx * 128 * GK, bq, qkvC, N3D, bx * 128, by * 128, 0);
    } else {
        int b2 = bx - N3D / 128;
        gemm_core(smem, xh + (size_t)by * 128 * GK, xl + (size_t)by * 128 * GK,
                  wg + (size_t)b2 * 128 * GK, bg, gateC, D2, b2 * 128, by * 128, 1);
    }
}

__global__ void __launch_bounds__(256, 1) gemm_proj(
    const __half* __restrict__ ath, const __half* __restrict__ atl,
    const __half* __restrict__ wp,  const float* __restrict__ bp,
    float* __restrict__ outC)
{
    extern __shared__ char smem[];
    int bx = blockIdx.x, by = blockIdx.y;
    gemm_core(smem, ath + (size_t)by * 128 * GK, atl + (size_t)by * 128 * GK,
              wp + (size_t)bx * 128 * GK, bp, outC, D2, bx * 128, by * 128, 0);
}

// ---------------- prep: split qkv, apply gate to k, elu+1, head layout ----
__global__ void prep_kernel(const float* __restrict__ qkv,
                            const float* __restrict__ gate,
                            float* __restrict__ qf,
                            float* __restrict__ kf,
                            float* __restrict__ vf) {
    int idx = blockIdx.x * 256 + threadIdx.x;     // 0 .. BL*D2
    int bl = idx / D2;
    int c  = idx - bl * D2;
    int h = c >> 6, d = c & 63;
    int b = bl >> 10, l = bl & 1023;
    float q = qkv[(size_t)bl * N3D + c];
    float k = qkv[(size_t)bl * N3D + D2 + c] * gate[idx];
    float v = qkv[(size_t)bl * N3D + 2 * D2 + c];
    int o = ((b * H2 + h) * L2 + l) * DH + d;
    qf[o] = (q > 0.f) ? (q + 1.f) : expf(q);
    kf[o] = (k > 0.f) ? (k + 1.f) : expf(k);
    vf[o] = v;
}

// ---------------- per-chunk K^T V (64x64) and ksum (64) -------------------
__global__ void chunk_kv_kernel(const float* __restrict__ kf,
                                const float* __restrict__ vf,
                                float* __restrict__ kv,
                                float* __restrict__ ksum) {
    __shared__ float Ks[32][64];
    __shared__ float Vs[32][64];
    int c = blockIdx.x, bh = blockIdx.y;
    int tid = threadIdx.x;   // 256
    const float* kp = kf + (size_t)(bh * L2 + c * CHK) * DH;
    const float* vp = vf + (size_t)(bh * L2 + c * CHK) * DH;
    int j = tid & 63;
    int ibase = tid >> 6;    // 0..3
    float acc[16];
    #pragma unroll
    for (int r = 0; r < 16; r++) acc[r] = 0.f;
    float ks = 0.f;
    for (int tt = 0; tt < 4; tt++) {
        for (int i = tid; i < 512; i += 256) {
            int row = i >> 4, col = (i & 15) << 2;
            *(float4*)&Ks[row][col] = *(const float4*)(kp + (size_t)(tt*32 + row)*DH + col);
            *(float4*)&Vs[row][col] = *(const float4*)(vp + (size_t)(tt*32 + row)*DH + col);
        }
        __syncthreads();
        #pragma unroll 4
        for (int t = 0; t < 32; t++) {
            float vj = Vs[t][j];
            #pragma unroll
            for (int r = 0; r < 16; r++)
                acc[r] += Ks[t][ibase + 4 * r] * vj;
        }
        if (tid < 64) {
            #pragma unroll 4
            for (int t = 0; t < 32; t++) ks += Ks[t][tid];
        }
        __syncthreads();
    }
    float* kvp = kv + (size_t)(bh * NC + c) * DH * DH;
    #pragma unroll
    for (int r = 0; r < 16; r++)
        kvp[(ibase + 4 * r) * DH + j] = acc[r];
    if (tid < 64) ksum[(bh * NC + c) * DH + tid] = ks;
}

// ---------------- exclusive prefix over chunks ----------------------------
__global__ void scan_kernel(const float* __restrict__ kv,
                            const float* __restrict__ ksum,
                            float* __restrict__ sprev,
                            float* __restrict__ ksp) {
    int bh = blockIdx.x;
    int tid = threadIdx.x;  // 256
    #pragma unroll
    for (int r = 0; r < 16; r++) {
        int e = tid + 256 * r;
        float acc = 0.f;
        #pragma unroll
        for (int c = 0; c < NC; c++) {
            size_t o = (size_t)(bh * NC + c) * DH * DH + e;
            sprev[o] = acc;
            acc += kv[o];
        }
    }
    if (tid < 64) {
        float acc = 0.f;
        #pragma unroll
        for (int c = 0; c < NC; c++) {
            size_t o = (size_t)(bh * NC + c) * DH + tid;
            ksp[o] = acc;
            acc += ksum[o];
        }
    }
}

// ---------------- per-chunk attention output ------------------------------
#define SM_Q   0
#define SM_K   (128*65)
#define SM_V   (SM_K + 128*65)
#define SM_A   (SM_V + 128*64)
#define SM_S   (SM_A + 128*129)
#define SM_KS  (SM_S + 64*64)
#define SM_DEN (SM_KS + 64)
#define ATTN_SMEM_FLOATS (SM_DEN + 128)

__global__ void attn_kernel(const float* __restrict__ qf,
                            const float* __restrict__ kf,
                            const float* __restrict__ vf,
                            const float* __restrict__ sprev,
                            const float* __restrict__ ksp,
                            __half* __restrict__ aoh,
                            __half* __restrict__ aol) {
    extern __shared__ float sm[];
    float* Qs = sm + SM_Q;
    float* Ks = sm + SM_K;
    float* Vs = sm + SM_V;
    float* As = sm + SM_A;
    float* Ss = sm + SM_S;
    float* Kp = sm + SM_KS;
    float* Dn = sm + SM_DEN;
    int c = blockIdx.x, bh = blockIdx.y;
    int tid = threadIdx.x;   // 256
    const float* qp = qf + (size_t)(bh * L2 + c * CHK) * DH;
    const float* kp = kf + (size_t)(bh * L2 + c * CHK) * DH;
    const float* vp = vf + (size_t)(bh * L2 + c * CHK) * DH;
    for (int i = tid; i < 2048; i += 256) {
        int row = i >> 4, col = (i & 15) << 2;
        float4 q4 = *(const float4*)(qp + (size_t)row * DH + col);
        float4 k4 = *(const float4*)(kp + (size_t)row * DH + col);
        float* qd = Qs + row * 65 + col;
        float* kd = Ks + row * 65 + col;
        qd[0]=q4.x; qd[1]=q4.y; qd[2]=q4.z; qd[3]=q4.w;
        kd[0]=k4.x; kd[1]=k4.y; kd[2]=k4.z; kd[3]=k4.w;
        *(float4*)(Vs + row * DH + col) = *(const float4*)(vp + (size_t)row * DH + col);
    }
    {
        const float4* sp = (const float4*)(sprev + (size_t)(bh * NC + c) * DH * DH);
        for (int i = tid; i < 1024; i += 256) ((float4*)Ss)[i] = sp[i];
        if (tid < 16)
            ((float4*)Kp)[tid] = ((const float4*)(ksp + (size_t)(bh * NC + c) * DH))[tid];
    }
    __syncthreads();
    {
        int aj = tid & 127;
        int ib = tid >> 7;
        for (int r = 0; r < 64; r++) {
            int ai = ib + 2 * r;
            float acc = 0.f;
            if (aj <= ai) {
                const float* qr = Qs + ai * 65;
                const float* kr = Ks + aj * 65;
                #pragma unroll
                for (int d = 0; d < 64; d++) acc += qr[d] * kr[d];
            }
            As[ai * 129 + aj] = acc;
        }
    }
    __syncthreads();
    if (tid < 128) {
        float s = 0.f;
        const float* ar = As + tid * 129;
        for (int j = 0; j <= tid; j++) s += ar[j];
        const float* qr = Qs + tid * 65;
        float qk = 0.f;
        #pragma unroll
        for (int d = 0; d < 64; d++) qk += qr[d] * Kp[d];
        Dn[tid] = s + qk + 1e-6f;
    }
    __syncthreads();
    {
        int oj = tid & 63;
        int ob = tid >> 6;
        int b = bh / H2, h = bh - b * H2;
        for (int r = 0; r < 32; r++) {
            int oi = ob + 4 * r;
            float acc = 0.f;
            const float* ar = As + oi * 129;
            for (int t = 0; t <= oi; t++) acc += ar[t] * Vs[t * DH + oj];
            const float* qr = Qs + oi * 65;
            #pragma unroll
            for (int d = 0; d < 64; d++) acc += qr[d] * Ss[d * DH + oj];
            int l = c * CHK + oi;
            float val = acc / Dn[oi];
            __half hv, lv; split1h(val, hv, lv);
            size_t o = (size_t)(b * L2 + l) * D2 + h * DH + oj;
            aoh[o] = hv; aol[o] = lv;
        }
    }
}

// ---------------- launch ---------------------------------------------------
extern "C" void kernel_launch(void* const* d_in, const int* in_sizes, int n_in,
                              void* d_out, int out_size) {
    const float* x      = (const float*)d_in[0];
    const float* W_qkv  = (const float*)d_in[1];
    const float* b_qkv  = (const float*)d_in[2];
    const float* W_gate = (const float*)d_in[3];
    const float* b_gate = (const float*)d_in[4];
    const float* W_proj = (const float*)d_in[5];
    const float* b_proj = (const float*)d_in[6];
    const float* ln_g   = (const float*)d_in[7];
    const float* ln_b   = (const float*)d_in[8];
    float* out  = (float*)d_out;           // proj output
    float* gate = out + OUT_ELEMS;         // gate output (2nd return value)

    float *p_qkv, *p_qf, *p_kf, *p_vf, *p_kv, *p_ksum, *p_sprev, *p_ksp;
    __half *p_ah, *p_al, *p_xh, *p_xl, *p_ath, *p_atl;
    __half *p_wtq, *p_wtg, *p_wtp;
    cudaGetSymbolAddress((void**)&p_qkv,   g_qkv);
    cudaGetSymbolAddress((void**)&p_qf,    g_qf);
    cudaGetSymbolAddress((void**)&p_kf,    g_kf);
    cudaGetSymbolAddress((void**)&p_vf,    g_vf);
    cudaGetSymbolAddress((void**)&p_kv,    g_kv);
    cudaGetSymbolAddress((void**)&p_ksum,  g_ksum);
    cudaGetSymbolAddress((void**)&p_sprev, g_sprev);
    cudaGetSymbolAddress((void**)&p_ksp,   g_ksp);
    cudaGetSymbolAddress((void**)&p_ah,    g_ah);
    cudaGetSymbolAddress((void**)&p_al,    g_al);
    cudaGetSymbolAddress((void**)&p_xh,    g_xh);
    cudaGetSymbolAddress((void**)&p_xl,    g_xl);
    cudaGetSymbolAddress((void**)&p_ath,   g_ath);
    cudaGetSymbolAddress((void**)&p_atl,   g_atl);
    cudaGetSymbolAddress((void**)&p_wtq,   g_wtq);
    cudaGetSymbolAddress((void**)&p_wtg,   g_wtg);
    cudaGetSymbolAddress((void**)&p_wtp,   g_wtp);

    cudaFuncSetAttribute(gemm_qkv_gate, cudaFuncAttributeMaxDynamicSharedMemorySize,
                         GEMM_SMEM_BYTES);
    cudaFuncSetAttribute(gemm_proj, cudaFuncAttributeMaxDynamicSharedMemorySize,
                         GEMM_SMEM_BYTES);
    cudaFuncSetAttribute(attn_kernel, cudaFuncAttributeMaxDynamicSharedMemorySize,
                         ATTN_SMEM_FLOATS * 4);

    // 0. transpose weights -> [N, K] fp16
    transpose_kernel<<<dim3(N3D / 32, GK / 32), dim3(32, 8)>>>(W_qkv, p_wtq, GK, N3D);
    transpose_kernel<<<dim3(D2  / 32, GK / 32), dim3(32, 8)>>>(W_gate, p_wtg, GK, D2);
    transpose_kernel<<<dim3(D2  / 32, GK / 32), dim3(32, 8)>>>(W_proj, p_wtp, GK, D2);

    // 1. LayerNorm (fused fp16 split) + raw-x split
    ln_kernel<<<BL, 256>>>(x, ln_g, ln_b, p_ah, p_al);
    xsplit_kernel<<<(BL * D2) / 256, 256>>>(x, p_xh, p_xl);

    // 2+3. fused: qkv = xn @ W_qkv + b_qkv ; gate = sigmoid(x @ W_gate + b_gate)
    gemm_qkv_gate<<<dim3(N3D / 128 + D2 / 128, BL / 128), 256, GEMM_SMEM_BYTES>>>(
        p_ah, p_al, p_wtq, b_qkv, p_qkv,
        p_xh, p_xl, p_wtg, b_gate, gate);

    // 4. split / gate-k / elu+1 / head layout
    prep_kernel<<<(BL * D2) / 256, 256>>>(p_qkv, gate, p_qf, p_kf, p_vf);

    // 5. per-chunk K^T V and ksum
    chunk_kv_kernel<<<dim3(NC, BH), 256>>>(p_kf, p_vf, p_kv, p_ksum);

    // 6. exclusive prefix over chunks
    scan_kernel<<<BH, 256>>>(p_kv, p_ksum, p_sprev, p_ksp);

    // 7. per-chunk attention (fused fp16 split of output)
    attn_kernel<<<dim3(NC, BH), 256, ATTN_SMEM_FLOATS * 4>>>(
        p_qf, p_kf, p_vf, p_sprev, p_ksp, p_ath, p_atl);

    // 8. out = attn @ W_proj + b_proj
    gemm_proj<<<dim3(D2 / 128, BL / 128), 256, GEMM_SMEM_BYTES>>>(
        p_ath, p_atl, p_wtp, b_proj, out);
}

// round 7
// speedup vs baseline: 2.3116x; 1.0121x over previous
#include <cuda_runtime.h>
#include <cuda_fp16.h>
#include <math.h>
#include <stdint.h>

// Problem constants
#define B2   2
#define L2   1024
#define D2   768
#define H2   12
#define DH   64
#define BH   (B2*H2)        // 24
#define BL   (B2*L2)        // 2048
#define N3D  (3*D2)         // 2304
#define CHK  128            // chunk length
#define NC   (L2/CHK)       // 8
#define GK   768            // shared K dim of all GEMMs
#define OUT_ELEMS (BL*D2)   // 1572864

// ---------------- scratch (device globals; no allocation allowed) ----------
__device__ float g_qkv[BL*N3D];
__device__ float g_qf[BH*L2*DH];
__device__ float g_kf[BH*L2*DH];
__device__ float g_vf[BH*L2*DH];
__device__ float g_kv[BH*NC*DH*DH];
__device__ float g_ksum[BH*NC*DH];
__device__ float g_sprev[BH*NC*DH*DH];
__device__ float g_ksp[BH*NC*DH];
// fp16 pre-split operands (16B-aligned for cp.async)
__device__ __align__(256) __half g_ah[BL*GK];       // LN(x) hi
__device__ __align__(256) __half g_al[BL*GK];       // LN(x) lo
__device__ __align__(256) __half g_xh[BL*GK];       // raw x hi
__device__ __align__(256) __half g_xl[BL*GK];       // raw x lo
__device__ __align__(256) __half g_ath[BL*D2];      // attn out hi
__device__ __align__(256) __half g_atl[BL*D2];      // attn out lo
__device__ __align__(256) __half g_wtq[N3D*GK];     // W_qkv^T fp16
__device__ __align__(256) __half g_wtg[D2*GK];      // W_gate^T fp16
__device__ __align__(256) __half g_wtp[D2*GK];      // W_proj^T fp16

// =================== helpers ===============================================
__device__ __forceinline__ uint32_t smem_u32(const void* p) {
    uint32_t a;
    asm("{ .reg .u64 t; cvta.to.shared.u64 t, %1; cvt.u32.u64 %0, t; }"
        : "=r"(a) : "l"(p));
    return a;
}
__device__ __forceinline__ uint32_t sw128(uint32_t off) {
    return off ^ ((off >> 3) & 0x70);
}
__device__ __forceinline__ void split1h(float v, __half& h, __half& l) {
    h = __float2half_rn(v);
    l = __float2half_rn(v - __half2float(h));
}

#define LDSM4(r0, r1, r2, r3, addr) \
    asm volatile("ldmatrix.sync.aligned.m8n8.x4.shared.b16 {%0,%1,%2,%3}, [%4];" \
        : "=r"(r0), "=r"(r1), "=r"(r2), "=r"(r3) : "r"(addr))

#define MMA_F16(d, a, b) \
    asm volatile("mma.sync.aligned.m16n8k16.row.col.f32.f16.f16.f32 " \
        "{%0,%1,%2,%3},{%4,%5,%6,%7},{%8,%9},{%0,%1,%2,%3};" \
        : "+f"((d)[0]), "+f"((d)[1]), "+f"((d)[2]), "+f"((d)[3]) \
        : "r"((a)[0]), "r"((a)[1]), "r"((a)[2]), "r"((a)[3]), \
          "r"((b)[0]), "r"((b)[1]))

#define CP_ASYNC16(dst, src) \
    asm volatile("cp.async.cg.shared.global [%0], [%1], 16;" \
        :: "r"((uint32_t)(dst)), "l"(src))
#define CP_COMMIT() asm volatile("cp.async.commit_group;" ::: "memory")
#define CP_WAIT(n)  asm volatile("cp.async.wait_group %0;" :: "n"(n) : "memory")

// ------- LayerNorm + fp16 hi/lo split of BOTH xn and raw x -----------------
__global__ void ln_kernel(const float* __restrict__ x,
                          const float* __restrict__ g,
                          const float* __restrict__ b,
                          __half* __restrict__ anh, __half* __restrict__ anl,
                          __half* __restrict__ xh,  __half* __restrict__ xl) {
    int row = blockIdx.x;
    int tid = threadIdx.x;  // 256
    const float* xr = x + row * D2;
    float v0 = xr[tid], v1 = xr[tid + 256], v2 = xr[tid + 512];
    float s  = v0 + v1 + v2;
    float sq = v0*v0 + v1*v1 + v2*v2;
    #pragma unroll
    for (int o = 16; o; o >>= 1) {
        s  += __shfl_xor_sync(0xffffffffu, s,  o);
        sq += __shfl_xor_sync(0xffffffffu, sq, o);
    }
    __shared__ float ss[8], sqs[8];
    if ((tid & 31) == 0) { ss[tid >> 5] = s; sqs[tid >> 5] = sq; }
    __syncthreads();
    float ts = 0.f, tq = 0.f;
    #pragma unroll
    for (int w = 0; w < 8; w++) { ts += ss[w]; tq += sqs[w]; }
    float mean = ts * (1.f / D2);
    float var  = tq * (1.f / D2) - mean * mean;
    float inv  = rsqrtf(var + 1e-5f);
    size_t base = (size_t)row * D2;
    #pragma unroll
    for (int p = 0; p < 3; p++) {
        int cc = tid + 256 * p;
        float v = (p == 0 ? v0 : (p == 1 ? v1 : v2));
        float xnv = (v - mean) * inv * g[cc] + b[cc];
        __half h, l;
        split1h(xnv, h, l);
        anh[base + cc] = h; anl[base + cc] = l;
        split1h(v, h, l);
        xh[base + cc] = h; xl[base + cc] = l;
    }
}

// ---------------- W[K,N] -> Wt[N,K] transpose to fp16 ----------------------
__global__ void transpose_kernel(const float* __restrict__ W,
                                 __half* __restrict__ Wt, int K, int N) {
    __shared__ float t[32][33];
    int n0 = blockIdx.x * 32, k0 = blockIdx.y * 32;
    int tx = threadIdx.x, ty = threadIdx.y;   // (32, 8)
    #pragma unroll
    for (int r = ty; r < 32; r += 8)
        t[r][tx] = W[(size_t)(k0 + r) * N + n0 + tx];
    __syncthreads();
    #pragma unroll
    for (int r = ty; r < 32; r += 8)
        Wt[(size_t)(n0 + r) * K + k0 + tx] = __float2half_rn(t[tx][r]);
}

// ---------------- fp16x2 mma.sync GEMM, 2-stage cp.async, occ 2 ------------
// C[M,N] = (Ah+Al)[M,768] @ Wt[N,768]^T + bias.
// BM=BN=128, BK=64. Stage (49152 B): Ah 16K | Al 16K | B 16K. SW128 rows=128B.
#define BKC 64
#define STG_AH 0
#define STG_AL 16384
#define STG_B  32768
#define STAGE_B 49152
#define NSTG 2
#define GEMM_SMEM_BYTES (NSTG * STAGE_B)   // 98304 -> 2 CTAs/SM
#define NCHUNK (GK / BKC)   // 12

__device__ __forceinline__ void gemm_core(char* smem,
    const __half* __restrict__ ApH, const __half* __restrict__ ApL,
    const __half* __restrict__ Bp,
    const float* __restrict__ bias, float* __restrict__ C,
    int Nld, int cb0, int rb0, int sig)
{
    uint32_t sb = smem_u32(smem);
    int tid  = threadIdx.x;
    int wid  = tid >> 5, lane = tid & 31;
    int wm   = wid >> 2, wn = wid & 3;        // warp grid 2x4
    int m0   = wm * 64;                       // warp tile 64x32
    int n0   = wn * 32;
    int lr   = lane & 7, g = lane >> 3;
    int arow = ((g & 1) << 3) + lr;
    int acolb = (g >> 1) << 4;
    int brow = ((g >> 1) << 3) + lr;
    int bcolb = (g & 1) << 4;

    // per-thread cp.async positions: 1024 16B segments per array, 4 per thread
    int srow[4], sseg[4]; uint32_t soff[4];
    #pragma unroll
    for (int i = 0; i < 4; i++) {
        int idx = tid + 256 * i;
        srow[i] = idx >> 3;
        sseg[i] = idx & 7;
        soff[i] = sw128((uint32_t)(srow[i] * 128 + sseg[i] * 16));
    }

    float acc[4][4][4];
    #pragma unroll
    for (int mt = 0; mt < 4; mt++)
        #pragma unroll
        for (int nt = 0; nt < 4; nt++)
            #pragma unroll
            for (int q = 0; q < 4; q++) acc[mt][nt][q] = 0.f;

    // prologue: issue chunk 0 into stage 0
    {
        uint32_t db = sb;
        #pragma unroll
        for (int i = 0; i < 4; i++) {
            size_t off = (size_t)srow[i] * GK + sseg[i] * 8;
            CP_ASYNC16(db + STG_AH + soff[i], ApH + off);
            CP_ASYNC16(db + STG_AL + soff[i], ApL + off);
            CP_ASYNC16(db + STG_B  + soff[i], Bp  + off);
        }
        CP_COMMIT();
    }

    for (int c = 0; c < NCHUNK; c++) {
        int st = c & 1;
        CP_WAIT(0);
        __syncthreads();
        if (c + 1 < NCHUNK) {
            uint32_t db = sb + (st ^ 1) * STAGE_B;
            int k0 = (c + 1) * BKC;
            #pragma unroll
            for (int i = 0; i < 4; i++) {
                size_t off = (size_t)srow[i] * GK + k0 + sseg[i] * 8;
                CP_ASYNC16(db + STG_AH + soff[i], ApH + off);
                CP_ASYNC16(db + STG_AL + soff[i], ApL + off);
                CP_ASYNC16(db + STG_B  + soff[i], Bp  + off);
            }
            CP_COMMIT();
        }

        uint32_t sA  = sb + st * STAGE_B;
        uint32_t sAl = sA + STG_AL;
        uint32_t sB  = sA + STG_B;
        #pragma unroll
        for (int kt = 0; kt < 4; kt++) {
            uint32_t bf[4][2];
            #pragma unroll
            for (int t = 0; t < 2; t++) {
                uint32_t boff = sw128((uint32_t)((n0 + t * 16 + brow) * 128 + kt * 32 + bcolb));
                LDSM4(bf[2*t][0], bf[2*t][1], bf[2*t+1][0], bf[2*t+1][1], sB + boff);
            }
            #pragma unroll
            for (int mt = 0; mt < 4; mt++) {
                uint32_t aoff = sw128((uint32_t)((m0 + mt * 16 + arow) * 128 + kt * 32 + acolb));
                uint32_t ah[4], al[4];
                LDSM4(ah[0], ah[1], ah[2], ah[3], sA  + aoff);
                LDSM4(al[0], al[1], al[2], al[3], sAl + aoff);
                #pragma unroll
                for (int nt = 0; nt < 4; nt++) {
                    MMA_F16(acc[mt][nt], ah, bf[nt]);
                    MMA_F16(acc[mt][nt], al, bf[nt]);
                }
            }
        }
        __syncthreads();
    }

    // epilogue
    int rbase = rb0 + m0 + (lane >> 2);
    int cbase = cb0 + n0 + ((lane & 3) << 1);
    #pragma unroll
    for (int mt = 0; mt < 4; mt++) {
        #pragma unroll
        for (int nt = 0; nt < 4; nt++) {
            int col = cbase + nt * 8;
            float b0 = bias[col], b1 = bias[col + 1];
            #pragma unroll
            for (int h = 0; h < 2; h++) {
                int row = rbase + mt * 16 + h * 8;
                float o0 = acc[mt][nt][2*h + 0] + b0;
                float o1 = acc[mt][nt][2*h + 1] + b1;
                if (sig) {
                    o0 = 1.f / (1.f + expf(-o0));
                    o1 = 1.f / (1.f + expf(-o1));
                }
                *(float2*)(C + (size_t)row * Nld + col) = make_float2(o0, o1);
            }
        }
    }
}

// fused QKV + gate GEMM: bx<18 -> QKV tile, bx>=18 -> gate tile (sigmoid)
__global__ void __launch_bounds__(256, 2) gemm_qkv_gate(
    const __half* __restrict__ xnh, const __half* __restrict__ xnl,
    const __half* __restrict__ wq,  const float* __restrict__ bq,
    float* __restrict__ qkvC,
    const __half* __restrict__ xh,  const __half* __restrict__ xl,
    const __half* __restrict__ wg,  const float* __restrict__ bg,
    float* __restrict__ gateC)
{
    extern __shared__ char smem[];
    int bx = blockIdx.x, by = blockIdx.y;
    if (bx < N3D / 128) {
        gemm_core(smem, xnh + (size_t)by * 128 * GK, xnl + (size_t)by * 128 * GK,
                  wq + (size_t)bx * 128 * GK, bq, qkvC, N3D, bx * 128, by * 128, 0);
    } else {
        int b2 = bx - N3D / 128;
        gemm_core(smem, xh + (size_t)by * 128 * GK, xl + (size_t)by * 128 * GK,
                  wg + (size_t)b2 * 128 * GK, bg, gateC, D2, b2 * 128, by * 128, 1);
    }
}

__global__ void __launch_bounds__(256, 2) gemm_proj(
    const __half* __restrict__ ath, const __half* __restrict__ atl,
    const __half* __restrict__ wp,  const float* __restrict__ bp,
    float* __restrict__ outC)
{
    extern __shared__ char smem[];
    int bx = blockIdx.x, by = blockIdx.y;
    gemm_core(smem, ath + (size_t)by * 128 * GK, atl + (size_t)by * 128 * GK,
              wp + (size_t)bx * 128 * GK, bp, outC, D2, bx * 128, by * 128, 0);
}

// ---------------- prep: split qkv, apply gate to k, elu+1, head layout ----
__global__ void prep_kernel(const float* __restrict__ qkv,
                            const float* __restrict__ gate,
                            float* __restrict__ qf,
                            float* __restrict__ kf,
                            float* __restrict__ vf) {
    int idx = blockIdx.x * 256 + threadIdx.x;     // 0 .. BL*D2
    int bl = idx / D2;
    int c  = idx - bl * D2;
    int h = c >> 6, d = c & 63;
    int b = bl >> 10, l = bl & 1023;
    float q = qkv[(size_t)bl * N3D + c];
    float k = qkv[(size_t)bl * N3D + D2 + c] * gate[idx];
    float v = qkv[(size_t)bl * N3D + 2 * D2 + c];
    int o = ((b * H2 + h) * L2 + l) * DH + d;
    qf[o] = (q > 0.f) ? (q + 1.f) : expf(q);
    kf[o] = (k > 0.f) ? (k + 1.f) : expf(k);
    vf[o] = v;
}

// ---------------- per-chunk K^T V (64x64) and ksum (64) -------------------
__global__ void chunk_kv_kernel(const float* __restrict__ kf,
                                const float* __restrict__ vf,
                                float* __restrict__ kv,
                                float* __restrict__ ksum) {
    __shared__ float Ks[32][64];
    __shared__ float Vs[32][64];
    int c = blockIdx.x, bh = blockIdx.y;
    int tid = threadIdx.x;   // 256
    const float* kp = kf + (size_t)(bh * L2 + c * CHK) * DH;
    const float* vp = vf + (size_t)(bh * L2 + c * CHK) * DH;
    int j = tid & 63;
    int ibase = tid >> 6;    // 0..3
    float acc[16];
    #pragma unroll
    for (int r = 0; r < 16; r++) acc[r] = 0.f;
    float ks = 0.f;
    for (int tt = 0; tt < 4; tt++) {
        for (int i = tid; i < 512; i += 256) {
            int row = i >> 4, col = (i & 15) << 2;
            *(float4*)&Ks[row][col] = *(const float4*)(kp + (size_t)(tt*32 + row)*DH + col);
            *(float4*)&Vs[row][col] = *(const float4*)(vp + (size_t)(tt*32 + row)*DH + col);
        }
        __syncthreads();
        #pragma unroll 4
        for (int t = 0; t < 32; t++) {
            float vj = Vs[t][j];
            #pragma unroll
            for (int r = 0; r < 16; r++)
                acc[r] += Ks[t][ibase + 4 * r] * vj;
        }
        if (tid < 64) {
            #pragma unroll 4
            for (int t = 0; t < 32; t++) ks += Ks[t][tid];
        }
        __syncthreads();
    }
    float* kvp = kv + (size_t)(bh * NC + c) * DH * DH;
    #pragma unroll
    for (int r = 0; r < 16; r++)
        kvp[(ibase + 4 * r) * DH + j] = acc[r];
    if (tid < 64) ksum[(bh * NC + c) * DH + tid] = ks;
}

// ---------------- exclusive prefix over chunks ----------------------------
__global__ void scan_kernel(const float* __restrict__ kv,
                            const float* __restrict__ ksum,
                            float* __restrict__ sprev,
                            float* __restrict__ ksp) {
    int bh = blockIdx.x;
    int tid = threadIdx.x;  // 256
    #pragma unroll
    for (int r = 0; r < 16; r++) {
        int e = tid + 256 * r;
        float acc = 0.f;
        #pragma unroll
        for (int c = 0; c < NC; c++) {
            size_t o = (size_t)(bh * NC + c) * DH * DH + e;
            sprev[o] = acc;
            acc += kv[o];
        }
    }
    if (tid < 64) {
        float acc = 0.f;
        #pragma unroll
        for (int c = 0; c < NC; c++) {
            size_t o = (size_t)(bh * NC + c) * DH + tid;
            ksp[o] = acc;
            acc += ksum[o];
        }
    }
}

// ---------------- per-chunk attention output ------------------------------
#define SM_Q   0
#define SM_K   (128*65)
#define SM_V   (SM_K + 128*65)
#define SM_A   (SM_V + 128*64)
#define SM_S   (SM_A + 128*129)
#define SM_KS  (SM_S + 64*64)
#define SM_DEN (SM_KS + 64)
#define ATTN_SMEM_FLOATS (SM_DEN + 128)

__global__ void attn_kernel(const float* __restrict__ qf,
                            const float* __restrict__ kf,
                            const float* __restrict__ vf,
                            const float* __restrict__ sprev,
                            const float* __restrict__ ksp,
                            __half* __restrict__ aoh,
                            __half* __restrict__ aol) {
    extern __shared__ float sm[];
    float* Qs = sm + SM_Q;
    float* Ks = sm + SM_K;
    float* Vs = sm + SM_V;
    float* As = sm + SM_A;
    float* Ss = sm + SM_S;
    float* Kp = sm + SM_KS;
    float* Dn = sm + SM_DEN;
    int c = blockIdx.x, bh = blockIdx.y;
    int tid = threadIdx.x;   // 256
    const float* qp = qf + (size_t)(bh * L2 + c * CHK) * DH;
    const float* kp = kf + (size_t)(bh * L2 + c * CHK) * DH;
    const float* vp = vf + (size_t)(bh * L2 + c * CHK) * DH;
    for (int i = tid; i < 2048; i += 256) {
        int row = i >> 4, col = (i & 15) << 2;
        float4 q4 = *(const float4*)(qp + (size_t)row * DH + col);
        float4 k4 = *(const float4*)(kp + (size_t)row * DH + col);
        float* qd = Qs + row * 65 + col;
        float* kd = Ks + row * 65 + col;
        qd[0]=q4.x; qd[1]=q4.y; qd[2]=q4.z; qd[3]=q4.w;
        kd[0]=k4.x; kd[1]=k4.y; kd[2]=k4.z; kd[3]=k4.w;
        *(float4*)(Vs + row * DH + col) = *(const float4*)(vp + (size_t)row * DH + col);
    }
    {
        const float4* sp = (const float4*)(sprev + (size_t)(bh * NC + c) * DH * DH);
        for (int i = tid; i < 1024; i += 256) ((float4*)Ss)[i] = sp[i];
        if (tid < 16)
            ((float4*)Kp)[tid] = ((const float4*)(ksp + (size_t)(bh * NC + c) * DH))[tid];
    }
    __syncthreads();
    {
        int aj = tid & 127;
        int ib = tid >> 7;
        for (int r = 0; r < 64; r++) {
            int ai = ib + 2 * r;
            float acc = 0.f;
            if (aj <= ai) {
                const float* qr = Qs + ai * 65;
                const float* kr = Ks + aj * 65;
                #pragma unroll
                for (int d = 0; d < 64; d++) acc += qr[d] * kr[d];
            }
            As[ai * 129 + aj] = acc;
        }
    }
    __syncthreads();
    if (tid < 128) {
        float s = 0.f;
        const float* ar = As + tid * 129;
        for (int j = 0; j <= tid; j++) s += ar[j];
        const float* qr = Qs + tid * 65;
        float qk = 0.f;
        #pragma unroll
        for (int d = 0; d < 64; d++) qk += qr[d] * Kp[d];
        Dn[tid] = s + qk + 1e-6f;
    }
    __syncthreads();
    {
        int oj = tid & 63;
        int ob = tid >> 6;
        int b = bh / H2, h = bh - b * H2;
        for (int r = 0; r < 32; r++) {
            int oi = ob + 4 * r;
            float acc = 0.f;
            const float* ar = As + oi * 129;
            for (int t = 0; t <= oi; t++) acc += ar[t] * Vs[t * DH + oj];
            const float* qr = Qs + oi * 65;
            #pragma unroll
            for (int d = 0; d < 64; d++) acc += qr[d] * Ss[d * DH + oj];
            int l = c * CHK + oi;
            float val = acc / Dn[oi];
            __half hv, lv; split1h(val, hv, lv);
            size_t o = (size_t)(b * L2 + l) * D2 + h * DH + oj;
            aoh[o] = hv; aol[o] = lv;
        }
    }
}

// ---------------- launch ---------------------------------------------------
extern "C" void kernel_launch(void* const* d_in, const int* in_sizes, int n_in,
                              void* d_out, int out_size) {
    const float* x      = (const float*)d_in[0];
    const float* W_qkv  = (const float*)d_in[1];
    const float* b_qkv  = (const float*)d_in[2];
    const float* W_gate = (const float*)d_in[3];
    const float* b_gate = (const float*)d_in[4];
    const float* W_proj = (const float*)d_in[5];
    const float* b_proj = (const float*)d_in[6];
    const float* ln_g   = (const float*)d_in[7];
    const float* ln_b   = (const float*)d_in[8];
    float* out  = (float*)d_out;           // proj output
    float* gate = out + OUT_ELEMS;         // gate output (2nd return value)

    float *p_qkv, *p_qf, *p_kf, *p_vf, *p_kv, *p_ksum, *p_sprev, *p_ksp;
    __half *p_ah, *p_al, *p_xh, *p_xl, *p_ath, *p_atl;
    __half *p_wtq, *p_wtg, *p_wtp;
    cudaGetSymbolAddress((void**)&p_qkv,   g_qkv);
    cudaGetSymbolAddress((void**)&p_qf,    g_qf);
    cudaGetSymbolAddress((void**)&p_kf,    g_kf);
    cudaGetSymbolAddress((void**)&p_vf,    g_vf);
    cudaGetSymbolAddress((void**)&p_kv,    g_kv);
    cudaGetSymbolAddress((void**)&p_ksum,  g_ksum);
    cudaGetSymbolAddress((void**)&p_sprev, g_sprev);
    cudaGetSymbolAddress((void**)&p_ksp,   g_ksp);
    cudaGetSymbolAddress((void**)&p_ah,    g_ah);
    cudaGetSymbolAddress((void**)&p_al,    g_al);
    cudaGetSymbolAddress((void**)&p_xh,    g_xh);
    cudaGetSymbolAddress((void**)&p_xl,    g_xl);
    cudaGetSymbolAddress((void**)&p_ath,   g_ath);
    cudaGetSymbolAddress((void**)&p_atl,   g_atl);
    cudaGetSymbolAddress((void**)&p_wtq,   g_wtq);
    cudaGetSymbolAddress((void**)&p_wtg,   g_wtg);
    cudaGetSymbolAddress((void**)&p_wtp,   g_wtp);

    cudaFuncSetAttribute(gemm_qkv_gate, cudaFuncAttributeMaxDynamicSharedMemorySize,
                         GEMM_SMEM_BYTES);
    cudaFuncSetAttribute(gemm_proj, cudaFuncAttributeMaxDynamicSharedMemorySize,
                         GEMM_SMEM_BYTES);
    cudaFuncSetAttribute(attn_kernel, cudaFuncAttributeMaxDynamicSharedMemorySize,
                         ATTN_SMEM_FLOATS * 4);

    // 0. transpose weights -> [N, K] fp16
    transpose_kernel<<<dim3(N3D / 32, GK / 32), dim3(32, 8)>>>(W_qkv, p_wtq, GK, N3D);
    transpose_kernel<<<dim3(D2  / 32, GK / 32), dim3(32, 8)>>>(W_gate, p_wtg, GK, D2);
    transpose_kernel<<<dim3(D2  / 32, GK / 32), dim3(32, 8)>>>(W_proj, p_wtp, GK, D2);

    // 1. LayerNorm (fused fp16 split of xn AND raw x)
    ln_kernel<<<BL, 256>>>(x, ln_g, ln_b, p_ah, p_al, p_xh, p_xl);

    // 2+3. fused: qkv = xn @ W_qkv + b_qkv ; gate = sigmoid(x @ W_gate + b_gate)
    gemm_qkv_gate<<<dim3(N3D / 128 + D2 / 128, BL / 128), 256, GEMM_SMEM_BYTES>>>(
        p_ah, p_al, p_wtq, b_qkv, p_qkv,
        p_xh, p_xl, p_wtg, b_gate, gate);

    // 4. split / gate-k / elu+1 / head layout
    prep_kernel<<<(BL * D2) / 256, 256>>>(p_qkv, gate, p_qf, p_kf, p_vf);

    // 5. per-chunk K^T V and ksum
    chunk_kv_kernel<<<dim3(NC, BH), 256>>>(p_kf, p_vf, p_kv, p_ksum);

    // 6. exclusive prefix over chunks
    scan_kernel<<<BH, 256>>>(p_kv, p_ksum, p_sprev, p_ksp);

    // 7. per-chunk attention (fused fp16 split of output)
    attn_kernel<<<dim3(NC, BH), 256, ATTN_SMEM_FLOATS * 4>>>(
        p_qf, p_kf, p_vf, p_sprev, p_ksp, p_ath, p_atl);

    // 8. out = attn @ W_proj + b_proj
    gemm_proj<<<dim3(D2 / 128, BL / 128), 256, GEMM_SMEM_BYTES>>>(
        p_ath, p_atl, p_wtp, b_proj, out);
}

// round 8
// speedup vs baseline: 2.6327x; 1.1389x over previous
#include <cuda_runtime.h>
#include <cuda_fp16.h>
#include <math.h>
#include <stdint.h>

// Problem constants
#define B2   2
#define L2   1024
#define D2   768
#define H2   12
#define DH   64
#define BH   (B2*H2)        // 24
#define BL   (B2*L2)        // 2048
#define N3D  (3*D2)         // 2304
#define CHK  128            // chunk length
#define NC   (L2/CHK)       // 8
#define GK   768            // shared K dim of all GEMMs
#define OUT_ELEMS (BL*D2)   // 1572864

// ---------------- scratch (device globals; no allocation allowed) ----------
__device__ float g_qkv[BL*N3D];
__device__ float g_qf[BH*L2*DH];
__device__ float g_kf[BH*L2*DH];
__device__ float g_vf[BH*L2*DH];
__device__ float g_kv[BH*NC*DH*DH];
__device__ float g_ksum[BH*NC*DH];
__device__ float g_sprev[BH*NC*DH*DH];
__device__ float g_ksp[BH*NC*DH];
// fp16 operands (16B-aligned for cp.async)
__device__ __align__(256) __half g_an[BL*GK];       // LN(x) fp16
__device__ __align__(256) __half g_x16[BL*GK];      // raw x fp16
__device__ __align__(256) __half g_at16[BL*D2];     // attn out fp16
__device__ __align__(256) __half g_wtq[N3D*GK];     // W_qkv^T fp16
__device__ __align__(256) __half g_wtg[D2*GK];      // W_gate^T fp16
__device__ __align__(256) __half g_wtp[D2*GK];      // W_proj^T fp16

// =================== helpers ===============================================
__device__ __forceinline__ uint32_t smem_u32(const void* p) {
    uint32_t a;
    asm("{ .reg .u64 t; cvta.to.shared.u64 t, %1; cvt.u32.u64 %0, t; }"
        : "=r"(a) : "l"(p));
    return a;
}
__device__ __forceinline__ uint32_t sw128(uint32_t off) {
    return off ^ ((off >> 3) & 0x70);
}

#define LDSM4(r0, r1, r2, r3, addr) \
    asm volatile("ldmatrix.sync.aligned.m8n8.x4.shared.b16 {%0,%1,%2,%3}, [%4];" \
        : "=r"(r0), "=r"(r1), "=r"(r2), "=r"(r3) : "r"(addr))

#define MMA_F16(d, a, b) \
    asm volatile("mma.sync.aligned.m16n8k16.row.col.f32.f16.f16.f32 " \
        "{%0,%1,%2,%3},{%4,%5,%6,%7},{%8,%9},{%0,%1,%2,%3};" \
        : "+f"((d)[0]), "+f"((d)[1]), "+f"((d)[2]), "+f"((d)[3]) \
        : "r"((a)[0]), "r"((a)[1]), "r"((a)[2]), "r"((a)[3]), \
          "r"((b)[0]), "r"((b)[1]))

#define CP_ASYNC16(dst, src) \
    asm volatile("cp.async.cg.shared.global [%0], [%1], 16;" \
        :: "r"((uint32_t)(dst)), "l"(src))
#define CP_COMMIT() asm volatile("cp.async.commit_group;" ::: "memory")
#define CP_WAIT(n)  asm volatile("cp.async.wait_group %0;" :: "n"(n) : "memory")

// ------- LayerNorm -> fp16 xn, fp16 raw x ----------------------------------
__global__ void ln_kernel(const float* __restrict__ x,
                          const float* __restrict__ g,
                          const float* __restrict__ b,
                          __half* __restrict__ an, __half* __restrict__ x16) {
    int row = blockIdx.x;
    int tid = threadIdx.x;  // 256
    const float* xr = x + row * D2;
    float v0 = xr[tid], v1 = xr[tid + 256], v2 = xr[tid + 512];
    float s  = v0 + v1 + v2;
    float sq = v0*v0 + v1*v1 + v2*v2;
    #pragma unroll
    for (int o = 16; o; o >>= 1) {
        s  += __shfl_xor_sync(0xffffffffu, s,  o);
        sq += __shfl_xor_sync(0xffffffffu, sq, o);
    }
    __shared__ float ss[8], sqs[8];
    if ((tid & 31) == 0) { ss[tid >> 5] = s; sqs[tid >> 5] = sq; }
    __syncthreads();
    float ts = 0.f, tq = 0.f;
    #pragma unroll
    for (int w = 0; w < 8; w++) { ts += ss[w]; tq += sqs[w]; }
    float mean = ts * (1.f / D2);
    float var  = tq * (1.f / D2) - mean * mean;
    float inv  = rsqrtf(var + 1e-5f);
    size_t base = (size_t)row * D2;
    #pragma unroll
    for (int p = 0; p < 3; p++) {
        int cc = tid + 256 * p;
        float v = (p == 0 ? v0 : (p == 1 ? v1 : v2));
        float xnv = (v - mean) * inv * g[cc] + b[cc];
        an[base + cc]  = __float2half_rn(xnv);
        x16[base + cc] = __float2half_rn(v);
    }
}

// ---------------- W[K,N] -> Wt[N,K] transpose to fp16 ----------------------
__global__ void transpose_kernel(const float* __restrict__ W,
                                 __half* __restrict__ Wt, int K, int N) {
    __shared__ float t[32][33];
    int n0 = blockIdx.x * 32, k0 = blockIdx.y * 32;
    int tx = threadIdx.x, ty = threadIdx.y;   // (32, 8)
    #pragma unroll
    for (int r = ty; r < 32; r += 8)
        t[r][tx] = W[(size_t)(k0 + r) * N + n0 + tx];
    __syncthreads();
    #pragma unroll
    for (int r = ty; r < 32; r += 8)
        Wt[(size_t)(n0 + r) * K + k0 + tx] = __float2half_rn(t[tx][r]);
}

// ---------------- fp16 mma.sync GEMM, 2-stage cp.async, occ 2 --------------
// C[M,N] = A[M,768] @ Wt[N,768]^T + bias.
// BM=BN=128, BK=64. Stage (32768 B): A 16K | B 16K. SW128 rows=128B.
#define BKC 64
#define STG_A 0
#define STG_B 16384
#define STAGE_B 32768
#define NSTG 2
#define GEMM_SMEM_BYTES (NSTG * STAGE_B)   // 65536 -> 2+ CTAs/SM
#define NCHUNK (GK / BKC)   // 12

__device__ __forceinline__ void gemm_core(char* smem,
    const __half* __restrict__ Ap, const __half* __restrict__ Bp,
    const float* __restrict__ bias, float* __restrict__ C,
    int Nld, int cb0, int rb0, int sig)
{
    uint32_t sb = smem_u32(smem);
    int tid  = threadIdx.x;
    int wid  = tid >> 5, lane = tid & 31;
    int wm   = wid >> 2, wn = wid & 3;        // warp grid 2x4
    int m0   = wm * 64;                       // warp tile 64x32
    int n0   = wn * 32;
    int lr   = lane & 7, g = lane >> 3;
    int arow = ((g & 1) << 3) + lr;
    int acolb = (g >> 1) << 4;
    int brow = ((g >> 1) << 3) + lr;
    int bcolb = (g & 1) << 4;

    // per-thread cp.async positions: 1024 16B segments per array, 4 per thread
    int srow[4], sseg[4]; uint32_t soff[4];
    #pragma unroll
    for (int i = 0; i < 4; i++) {
        int idx = tid + 256 * i;
        srow[i] = idx >> 3;
        sseg[i] = idx & 7;
        soff[i] = sw128((uint32_t)(srow[i] * 128 + sseg[i] * 16));
    }

    float acc[4][4][4];
    #pragma unroll
    for (int mt = 0; mt < 4; mt++)
        #pragma unroll
        for (int nt = 0; nt < 4; nt++)
            #pragma unroll
            for (int q = 0; q < 4; q++) acc[mt][nt][q] = 0.f;

    // prologue: issue chunk 0 into stage 0
    {
        uint32_t db = sb;
        #pragma unroll
        for (int i = 0; i < 4; i++) {
            size_t off = (size_t)srow[i] * GK + sseg[i] * 8;
            CP_ASYNC16(db + STG_A + soff[i], Ap + off);
            CP_ASYNC16(db + STG_B + soff[i], Bp + off);
        }
        CP_COMMIT();
    }

    for (int c = 0; c < NCHUNK; c++) {
        int st = c & 1;
        CP_WAIT(0);
        __syncthreads();
        if (c + 1 < NCHUNK) {
            uint32_t db = sb + (st ^ 1) * STAGE_B;
            int k0 = (c + 1) * BKC;
            #pragma unroll
            for (int i = 0; i < 4; i++) {
                size_t off = (size_t)srow[i] * GK + k0 + sseg[i] * 8;
                CP_ASYNC16(db + STG_A + soff[i], Ap + off);
                CP_ASYNC16(db + STG_B + soff[i], Bp + off);
            }
            CP_COMMIT();
        }

        uint32_t sA = sb + st * STAGE_B;
        uint32_t sB = sA + STG_B;
        #pragma unroll
        for (int kt = 0; kt < 4; kt++) {
            uint32_t bf[4][2];
            #pragma unroll
            for (int t = 0; t < 2; t++) {
                uint32_t boff = sw128((uint32_t)((n0 + t * 16 + brow) * 128 + kt * 32 + bcolb));
                LDSM4(bf[2*t][0], bf[2*t][1], bf[2*t+1][0], bf[2*t+1][1], sB + boff);
            }
            #pragma unroll
            for (int mt = 0; mt < 4; mt++) {
                uint32_t aoff = sw128((uint32_t)((m0 + mt * 16 + arow) * 128 + kt * 32 + acolb));
                uint32_t af[4];
                LDSM4(af[0], af[1], af[2], af[3], sA + aoff);
                #pragma unroll
                for (int nt = 0; nt < 4; nt++)
                    MMA_F16(acc[mt][nt], af, bf[nt]);
            }
        }
        __syncthreads();
    }

    // epilogue
    int rbase = rb0 + m0 + (lane >> 2);
    int cbase = cb0 + n0 + ((lane & 3) << 1);
    #pragma unroll
    for (int mt = 0; mt < 4; mt++) {
        #pragma unroll
        for (int nt = 0; nt < 4; nt++) {
            int col = cbase + nt * 8;
            float b0 = bias[col], b1 = bias[col + 1];
            #pragma unroll
            for (int h = 0; h < 2; h++) {
                int row = rbase + mt * 16 + h * 8;
                float o0 = acc[mt][nt][2*h + 0] + b0;
                float o1 = acc[mt][nt][2*h + 1] + b1;
                if (sig) {
                    o0 = 1.f / (1.f + expf(-o0));
                    o1 = 1.f / (1.f + expf(-o1));
                }
                *(float2*)(C + (size_t)row * Nld + col) = make_float2(o0, o1);
            }
        }
    }
}

// fused QKV + gate GEMM: bx<18 -> QKV tile, bx>=18 -> gate tile (sigmoid)
__global__ void __launch_bounds__(256, 2) gemm_qkv_gate(
    const __half* __restrict__ xn,  const __half* __restrict__ wq,
    const float* __restrict__ bq,   float* __restrict__ qkvC,
    const __half* __restrict__ x16, const __half* __restrict__ wg,
    const float* __restrict__ bg,   float* __restrict__ gateC)
{
    extern __shared__ char smem[];
    int bx = blockIdx.x, by = blockIdx.y;
    if (bx < N3D / 128) {
        gemm_core(smem, xn + (size_t)by * 128 * GK,
                  wq + (size_t)bx * 128 * GK, bq, qkvC, N3D, bx * 128, by * 128, 0);
    } else {
        int b2 = bx - N3D / 128;
        gemm_core(smem, x16 + (size_t)by * 128 * GK,
                  wg + (size_t)b2 * 128 * GK, bg, gateC, D2, b2 * 128, by * 128, 1);
    }
}

__global__ void __launch_bounds__(256, 2) gemm_proj(
    const __half* __restrict__ at16, const __half* __restrict__ wp,
    const float* __restrict__ bp,    float* __restrict__ outC)
{
    extern __shared__ char smem[];
    int bx = blockIdx.x, by = blockIdx.y;
    gemm_core(smem, at16 + (size_t)by * 128 * GK,
              wp + (size_t)bx * 128 * GK, bp, outC, D2, bx * 128, by * 128, 0);
}

// ---------------- prep: split qkv, apply gate to k, elu+1, head layout ----
__global__ void prep_kernel(const float* __restrict__ qkv,
                            const float* __restrict__ gate,
                            float* __restrict__ qf,
                            float* __restrict__ kf,
                            float* __restrict__ vf) {
    int idx = blockIdx.x * 256 + threadIdx.x;     // 0 .. BL*D2
    int bl = idx / D2;
    int c  = idx - bl * D2;
    int h = c >> 6, d = c & 63;
    int b = bl >> 10, l = bl & 1023;
    float q = qkv[(size_t)bl * N3D + c];
    float k = qkv[(size_t)bl * N3D + D2 + c] * gate[idx];
    float v = qkv[(size_t)bl * N3D + 2 * D2 + c];
    int o = ((b * H2 + h) * L2 + l) * DH + d;
    qf[o] = (q > 0.f) ? (q + 1.f) : expf(q);
    kf[o] = (k > 0.f) ? (k + 1.f) : expf(k);
    vf[o] = v;
}

// ---------------- per-chunk K^T V (64x64) and ksum (64) -------------------
__global__ void chunk_kv_kernel(const float* __restrict__ kf,
                                const float* __restrict__ vf,
                                float* __restrict__ kv,
                                float* __restrict__ ksum) {
    __shared__ float Ks[32][64];
    __shared__ float Vs[32][64];
    int c = blockIdx.x, bh = blockIdx.y;
    int tid = threadIdx.x;   // 256
    const float* kp = kf + (size_t)(bh * L2 + c * CHK) * DH;
    const float* vp = vf + (size_t)(bh * L2 + c * CHK) * DH;
    int j = tid & 63;
    int ibase = tid >> 6;    // 0..3
    float acc[16];
    #pragma unroll
    for (int r = 0; r < 16; r++) acc[r] = 0.f;
    float ks = 0.f;
    for (int tt = 0; tt < 4; tt++) {
        for (int i = tid; i < 512; i += 256) {
            int row = i >> 4, col = (i & 15) << 2;
            *(float4*)&Ks[row][col] = *(const float4*)(kp + (size_t)(tt*32 + row)*DH + col);
            *(float4*)&Vs[row][col] = *(const float4*)(vp + (size_t)(tt*32 + row)*DH + col);
        }
        __syncthreads();
        #pragma unroll 4
        for (int t = 0; t < 32; t++) {
            float vj = Vs[t][j];
            #pragma unroll
            for (int r = 0; r < 16; r++)
                acc[r] += Ks[t][ibase + 4 * r] * vj;
        }
        if (tid < 64) {
            #pragma unroll 4
            for (int t = 0; t < 32; t++) ks += Ks[t][tid];
        }
        __syncthreads();
    }
    float* kvp = kv + (size_t)(bh * NC + c) * DH * DH;
    #pragma unroll
    for (int r = 0; r < 16; r++)
        kvp[(ibase + 4 * r) * DH + j] = acc[r];
    if (tid < 64) ksum[(bh * NC + c) * DH + tid] = ks;
}

// ---------------- exclusive prefix over chunks ----------------------------
__global__ void scan_kernel(const float* __restrict__ kv,
                            const float* __restrict__ ksum,
                            float* __restrict__ sprev,
                            float* __restrict__ ksp) {
    int bh = blockIdx.x;
    int tid = threadIdx.x;  // 256
    #pragma unroll
    for (int r = 0; r < 16; r++) {
        int e = tid + 256 * r;
        float acc = 0.f;
        #pragma unroll
        for (int c = 0; c < NC; c++) {
            size_t o = (size_t)(bh * NC + c) * DH * DH + e;
            sprev[o] = acc;
            acc += kv[o];
        }
    }
    if (tid < 64) {
        float acc = 0.f;
        #pragma unroll
        for (int c = 0; c < NC; c++) {
            size_t o = (size_t)(bh * NC + c) * DH + tid;
            ksp[o] = acc;
            acc += ksum[o];
        }
    }
}

// ---------------- per-chunk attention output ------------------------------
#define SM_Q   0
#define SM_K   (128*65)
#define SM_V   (SM_K + 128*65)
#define SM_A   (SM_V + 128*64)
#define SM_S   (SM_A + 128*129)
#define SM_KS  (SM_S + 64*64)
#define SM_DEN (SM_KS + 64)
#define ATTN_SMEM_FLOATS (SM_DEN + 128)

__global__ void attn_kernel(const float* __restrict__ qf,
                            const float* __restrict__ kf,
                            const float* __restrict__ vf,
                            const float* __restrict__ sprev,
                            const float* __restrict__ ksp,
                            __half* __restrict__ ao16) {
    extern __shared__ float sm[];
    float* Qs = sm + SM_Q;
    float* Ks = sm + SM_K;
    float* Vs = sm + SM_V;
    float* As = sm + SM_A;
    float* Ss = sm + SM_S;
    float* Kp = sm + SM_KS;
    float* Dn = sm + SM_DEN;
    int c = blockIdx.x, bh = blockIdx.y;
    int tid = threadIdx.x;   // 256
    const float* qp = qf + (size_t)(bh * L2 + c * CHK) * DH;
    const float* kp = kf + (size_t)(bh * L2 + c * CHK) * DH;
    const float* vp = vf + (size_t)(bh * L2 + c * CHK) * DH;
    for (int i = tid; i < 2048; i += 256) {
        int row = i >> 4, col = (i & 15) << 2;
        float4 q4 = *(const float4*)(qp + (size_t)row * DH + col);
        float4 k4 = *(const float4*)(kp + (size_t)row * DH + col);
        float* qd = Qs + row * 65 + col;
        float* kd = Ks + row * 65 + col;
        qd[0]=q4.x; qd[1]=q4.y; qd[2]=q4.z; qd[3]=q4.w;
        kd[0]=k4.x; kd[1]=k4.y; kd[2]=k4.z; kd[3]=k4.w;
        *(float4*)(Vs + row * DH + col) = *(const float4*)(vp + (size_t)row * DH + col);
    }
    {
        const float4* sp = (const float4*)(sprev + (size_t)(bh * NC + c) * DH * DH);
        for (int i = tid; i < 1024; i += 256) ((float4*)Ss)[i] = sp[i];
        if (tid < 16)
            ((float4*)Kp)[tid] = ((const float4*)(ksp + (size_t)(bh * NC + c) * DH))[tid];
    }
    __syncthreads();
    {
        int aj = tid & 127;
        int ib = tid >> 7;
        for (int r = 0; r < 64; r++) {
            int ai = ib + 2 * r;
            float acc = 0.f;
            if (aj <= ai) {
                const float* qr = Qs + ai * 65;
                const float* kr = Ks + aj * 65;
                #pragma unroll
                for (int d = 0; d < 64; d++) acc += qr[d] * kr[d];
            }
            As[ai * 129 + aj] = acc;
        }
    }
    __syncthreads();
    if (tid < 128) {
        float s = 0.f;
        const float* ar = As + tid * 129;
        for (int j = 0; j <= tid; j++) s += ar[j];
        const float* qr = Qs + tid * 65;
        float qk = 0.f;
        #pragma unroll
        for (int d = 0; d < 64; d++) qk += qr[d] * Kp[d];
        Dn[tid] = s + qk + 1e-6f;
    }
    __syncthreads();
    {
        int oj = tid & 63;
        int ob = tid >> 6;
        int b = bh / H2, h = bh - b * H2;
        for (int r = 0; r < 32; r++) {
            int oi = ob + 4 * r;
            float acc = 0.f;
            const float* ar = As + oi * 129;
            for (int t = 0; t <= oi; t++) acc += ar[t] * Vs[t * DH + oj];
            const float* qr = Qs + oi * 65;
            #pragma unroll
            for (int d = 0; d < 64; d++) acc += qr[d] * Ss[d * DH + oj];
            int l = c * CHK + oi;
            float val = acc / Dn[oi];
            size_t o = (size_t)(b * L2 + l) * D2 + h * DH + oj;
            ao16[o] = __float2half_rn(val);
        }
    }
}

// ---------------- launch ---------------------------------------------------
extern "C" void kernel_launch(void* const* d_in, const int* in_sizes, int n_in,
                              void* d_out, int out_size) {
    const float* x      = (const float*)d_in[0];
    const float* W_qkv  = (const float*)d_in[1];
    const float* b_qkv  = (const float*)d_in[2];
    const float* W_gate = (const float*)d_in[3];
    const float* b_gate = (const float*)d_in[4];
    const float* W_proj = (const float*)d_in[5];
    const float* b_proj = (const float*)d_in[6];
    const float* ln_g   = (const float*)d_in[7];
    const float* ln_b   = (const float*)d_in[8];
    float* out  = (float*)d_out;           // proj output
    float* gate = out + OUT_ELEMS;         // gate output (2nd return value)

    float *p_qkv, *p_qf, *p_kf, *p_vf, *p_kv, *p_ksum, *p_sprev, *p_ksp;
    __half *p_an, *p_x16, *p_at16, *p_wtq, *p_wtg, *p_wtp;
    cudaGetSymbolAddress((void**)&p_qkv,   g_qkv);
    cudaGetSymbolAddress((void**)&p_qf,    g_qf);
    cudaGetSymbolAddress((void**)&p_kf,    g_kf);
    cudaGetSymbolAddress((void**)&p_vf,    g_vf);
    cudaGetSymbolAddress((void**)&p_kv,    g_kv);
    cudaGetSymbolAddress((void**)&p_ksum,  g_ksum);
    cudaGetSymbolAddress((void**)&p_sprev, g_sprev);
    cudaGetSymbolAddress((void**)&p_ksp,   g_ksp);
    cudaGetSymbolAddress((void**)&p_an,    g_an);
    cudaGetSymbolAddress((void**)&p_x16,   g_x16);
    cudaGetSymbolAddress((void**)&p_at16,  g_at16);
    cudaGetSymbolAddress((void**)&p_wtq,   g_wtq);
    cudaGetSymbolAddress((void**)&p_wtg,   g_wtg);
    cudaGetSymbolAddress((void**)&p_wtp,   g_wtp);

    cudaFuncSetAttribute(gemm_qkv_gate, cudaFuncAttributeMaxDynamicSharedMemorySize,
                         GEMM_SMEM_BYTES);
    cudaFuncSetAttribute(gemm_proj, cudaFuncAttributeMaxDynamicSharedMemorySize,
                         GEMM_SMEM_BYTES);
    cudaFuncSetAttribute(attn_kernel, cudaFuncAttributeMaxDynamicSharedMemorySize,
                         ATTN_SMEM_FLOATS * 4);

    // 0. transpose weights -> [N, K] fp16
    transpose_kernel<<<dim3(N3D / 32, GK / 32), dim3(32, 8)>>>(W_qkv, p_wtq, GK, N3D);
    transpose_kernel<<<dim3(D2  / 32, GK / 32), dim3(32, 8)>>>(W_gate, p_wtg, GK, D2);
    transpose_kernel<<<dim3(D2  / 32, GK / 32), dim3(32, 8)>>>(W_proj, p_wtp, GK, D2);

    // 1. LayerNorm -> fp16 xn and fp16 raw x
    ln_kernel<<<BL, 256>>>(x, ln_g, ln_b, p_an, p_x16);

    // 2+3. fused: qkv = xn @ W_qkv + b_qkv ; gate = sigmoid(x @ W_gate + b_gate)
    gemm_qkv_gate<<<dim3(N3D / 128 + D2 / 128, BL / 128), 256, GEMM_SMEM_BYTES>>>(
        p_an, p_wtq, b_qkv, p_qkv,
        p_x16, p_wtg, b_gate, gate);

    // 4. split / gate-k / elu+1 / head layout
    prep_kernel<<<(BL * D2) / 256, 256>>>(p_qkv, gate, p_qf, p_kf, p_vf);

    // 5. per-chunk K^T V and ksum
    chunk_kv_kernel<<<dim3(NC, BH), 256>>>(p_kf, p_vf, p_kv, p_ksum);

    // 6. exclusive prefix over chunks
    scan_kernel<<<BH, 256>>>(p_kv, p_ksum, p_sprev, p_ksp);

    // 7. per-chunk attention (fp16 output)
    attn_kernel<<<dim3(NC, BH), 256, ATTN_SMEM_FLOATS * 4>>>(
        p_qf, p_kf, p_vf, p_sprev, p_ksp, p_at16);

    // 8. out = attn @ W_proj + b_proj
    gemm_proj<<<dim3(D2 / 128, BL / 128), 256, GEMM_SMEM_BYTES>>>(
        p_at16, p_wtp, b_proj, out);
}

// round 9
// speedup vs baseline: 6.0168x; 2.2854x over previous
#include <cuda_runtime.h>
#include <cuda_fp16.h>
#include <math.h>
#include <stdint.h>

// Problem constants
#define B2   2
#define L2   1024
#define D2   768
#define H2   12
#define DH   64
#define BH   (B2*H2)        // 24
#define BL   (B2*L2)        // 2048
#define N3D  (3*D2)         // 2304
#define CHK  128            // chunk length
#define NC   (L2/CHK)       // 8
#define GK   768            // shared K dim of all GEMMs
#define OUT_ELEMS (BL*D2)   // 1572864

// ---------------- scratch (device globals; no allocation allowed) ----------
__device__ float g_qkv[BL*N3D];
__device__ float g_kv[BH*NC*DH*DH];
__device__ float g_ksum[BH*NC*DH];
__device__ float g_sprev[BH*NC*DH*DH];
__device__ float g_ksp[BH*NC*DH];
// fp16 operands (16B-aligned for cp.async / vector loads)
__device__ __align__(256) __half g_an[BL*GK];       // LN(x) fp16
__device__ __align__(256) __half g_x16[BL*GK];      // raw x fp16
__device__ __align__(256) __half g_at16[BL*D2];     // attn out fp16
__device__ __align__(256) __half g_qf16[BH*L2*DH];
__device__ __align__(256) __half g_kf16[BH*L2*DH];
__device__ __align__(256) __half g_vf16[BH*L2*DH];
__device__ __align__(256) __half g_wtq[N3D*GK];     // W_qkv^T fp16
__device__ __align__(256) __half g_wtg[D2*GK];      // W_gate^T fp16
__device__ __align__(256) __half g_wtp[D2*GK];      // W_proj^T fp16

// =================== helpers ===============================================
__device__ __forceinline__ uint32_t smem_u32(const void* p) {
    uint32_t a;
    asm("{ .reg .u64 t; cvta.to.shared.u64 t, %1; cvt.u32.u64 %0, t; }"
        : "=r"(a) : "l"(p));
    return a;
}
__device__ __forceinline__ uint32_t sw128(uint32_t off) {
    return off ^ ((off >> 3) & 0x70);
}

#define LDSM4(r0, r1, r2, r3, addr) \
    asm volatile("ldmatrix.sync.aligned.m8n8.x4.shared.b16 {%0,%1,%2,%3}, [%4];" \
        : "=r"(r0), "=r"(r1), "=r"(r2), "=r"(r3) : "r"(addr))

#define MMA_F16(d, a, b) \
    asm volatile("mma.sync.aligned.m16n8k16.row.col.f32.f16.f16.f32 " \
        "{%0,%1,%2,%3},{%4,%5,%6,%7},{%8,%9},{%0,%1,%2,%3};" \
        : "+f"((d)[0]), "+f"((d)[1]), "+f"((d)[2]), "+f"((d)[3]) \
        : "r"((a)[0]), "r"((a)[1]), "r"((a)[2]), "r"((a)[3]), \
          "r"((b)[0]), "r"((b)[1]))

#define CP_ASYNC16(dst, src) \
    asm volatile("cp.async.cg.shared.global [%0], [%1], 16;" \
        :: "r"((uint32_t)(dst)), "l"(src))
#define CP_COMMIT() asm volatile("cp.async.commit_group;" ::: "memory")
#define CP_WAIT(n)  asm volatile("cp.async.wait_group %0;" :: "n"(n) : "memory")

// ------- LayerNorm -> fp16 xn, fp16 raw x ----------------------------------
__global__ void ln_kernel(const float* __restrict__ x,
                          const float* __restrict__ g,
                          const float* __restrict__ b,
                          __half* __restrict__ an, __half* __restrict__ x16) {
    int row = blockIdx.x;
    int tid = threadIdx.x;  // 256
    const float* xr = x + row * D2;
    float v0 = xr[tid], v1 = xr[tid + 256], v2 = xr[tid + 512];
    float s  = v0 + v1 + v2;
    float sq = v0*v0 + v1*v1 + v2*v2;
    #pragma unroll
    for (int o = 16; o; o >>= 1) {
        s  += __shfl_xor_sync(0xffffffffu, s,  o);
        sq += __shfl_xor_sync(0xffffffffu, sq, o);
    }
    __shared__ float ss[8], sqs[8];
    if ((tid & 31) == 0) { ss[tid >> 5] = s; sqs[tid >> 5] = sq; }
    __syncthreads();
    float ts = 0.f, tq = 0.f;
    #pragma unroll
    for (int w = 0; w < 8; w++) { ts += ss[w]; tq += sqs[w]; }
    float mean = ts * (1.f / D2);
    float var  = tq * (1.f / D2) - mean * mean;
    float inv  = rsqrtf(var + 1e-5f);
    size_t base = (size_t)row * D2;
    #pragma unroll
    for (int p = 0; p < 3; p++) {
        int cc = tid + 256 * p;
        float v = (p == 0 ? v0 : (p == 1 ? v1 : v2));
        float xnv = (v - mean) * inv * g[cc] + b[cc];
        an[base + cc]  = __float2half_rn(xnv);
        x16[base + cc] = __float2half_rn(v);
    }
}

// ---------------- W[K,N] -> Wt[N,K] transpose to fp16 ----------------------
__global__ void transpose_kernel(const float* __restrict__ W,
                                 __half* __restrict__ Wt, int K, int N) {
    __shared__ float t[32][33];
    int n0 = blockIdx.x * 32, k0 = blockIdx.y * 32;
    int tx = threadIdx.x, ty = threadIdx.y;   // (32, 8)
    #pragma unroll
    for (int r = ty; r < 32; r += 8)
        t[r][tx] = W[(size_t)(k0 + r) * N + n0 + tx];
    __syncthreads();
    #pragma unroll
    for (int r = ty; r < 32; r += 8)
        Wt[(size_t)(n0 + r) * K + k0 + tx] = __float2half_rn(t[tx][r]);
}

// ---------------- fp16 mma.sync GEMM, 2-stage cp.async ---------------------
#define BKC 64
#define STG_A 0
#define STG_B 16384
#define STAGE_B 32768
#define NSTG 2
#define GEMM_SMEM_BYTES (NSTG * STAGE_B)   // 65536
#define NCHUNK (GK / BKC)   // 12

__device__ __forceinline__ void gemm_core(char* smem,
    const __half* __restrict__ Ap, const __half* __restrict__ Bp,
    const float* __restrict__ bias, float* __restrict__ C,
    int Nld, int cb0, int rb0, int sig)
{
    uint32_t sb = smem_u32(smem);
    int tid  = threadIdx.x;
    int wid  = tid >> 5, lane = tid & 31;
    int wm   = wid >> 2, wn = wid & 3;        // warp grid 2x4
    int m0   = wm * 64;
    int n0   = wn * 32;
    int lr   = lane & 7, g = lane >> 3;
    int arow = ((g & 1) << 3) + lr;
    int acolb = (g >> 1) << 4;
    int brow = ((g >> 1) << 3) + lr;
    int bcolb = (g & 1) << 4;

    int srow[4], sseg[4]; uint32_t soff[4];
    #pragma unroll
    for (int i = 0; i < 4; i++) {
        int idx = tid + 256 * i;
        srow[i] = idx >> 3;
        sseg[i] = idx & 7;
        soff[i] = sw128((uint32_t)(srow[i] * 128 + sseg[i] * 16));
    }

    float acc[4][4][4];
    #pragma unroll
    for (int mt = 0; mt < 4; mt++)
        #pragma unroll
        for (int nt = 0; nt < 4; nt++)
            #pragma unroll
            for (int q = 0; q < 4; q++) acc[mt][nt][q] = 0.f;

    {
        uint32_t db = sb;
        #pragma unroll
        for (int i = 0; i < 4; i++) {
            size_t off = (size_t)srow[i] * GK + sseg[i] * 8;
            CP_ASYNC16(db + STG_A + soff[i], Ap + off);
            CP_ASYNC16(db + STG_B + soff[i], Bp + off);
        }
        CP_COMMIT();
    }

    for (int c = 0; c < NCHUNK; c++) {
        int st = c & 1;
        CP_WAIT(0);
        __syncthreads();
        if (c + 1 < NCHUNK) {
            uint32_t db = sb + (st ^ 1) * STAGE_B;
            int k0 = (c + 1) * BKC;
            #pragma unroll
            for (int i = 0; i < 4; i++) {
                size_t off = (size_t)srow[i] * GK + k0 + sseg[i] * 8;
                CP_ASYNC16(db + STG_A + soff[i], Ap + off);
                CP_ASYNC16(db + STG_B + soff[i], Bp + off);
            }
            CP_COMMIT();
        }

        uint32_t sA = sb + st * STAGE_B;
        uint32_t sB = sA + STG_B;
        #pragma unroll
        for (int kt = 0; kt < 4; kt++) {
            uint32_t bf[4][2];
            #pragma unroll
            for (int t = 0; t < 2; t++) {
                uint32_t boff = sw128((uint32_t)((n0 + t * 16 + brow) * 128 + kt * 32 + bcolb));
                LDSM4(bf[2*t][0], bf[2*t][1], bf[2*t+1][0], bf[2*t+1][1], sB + boff);
            }
            #pragma unroll
            for (int mt = 0; mt < 4; mt++) {
                uint32_t aoff = sw128((uint32_t)((m0 + mt * 16 + arow) * 128 + kt * 32 + acolb));
                uint32_t af[4];
                LDSM4(af[0], af[1], af[2], af[3], sA + aoff);
                #pragma unroll
                for (int nt = 0; nt < 4; nt++)
                    MMA_F16(acc[mt][nt], af, bf[nt]);
            }
        }
        __syncthreads();
    }

    int rbase = rb0 + m0 + (lane >> 2);
    int cbase = cb0 + n0 + ((lane & 3) << 1);
    #pragma unroll
    for (int mt = 0; mt < 4; mt++) {
        #pragma unroll
        for (int nt = 0; nt < 4; nt++) {
            int col = cbase + nt * 8;
            float b0 = bias[col], b1 = bias[col + 1];
            #pragma unroll
            for (int h = 0; h < 2; h++) {
                int row = rbase + mt * 16 + h * 8;
                float o0 = acc[mt][nt][2*h + 0] + b0;
                float o1 = acc[mt][nt][2*h + 1] + b1;
                if (sig) {
                    o0 = 1.f / (1.f + expf(-o0));
                    o1 = 1.f / (1.f + expf(-o1));
                }
                *(float2*)(C + (size_t)row * Nld + col) = make_float2(o0, o1);
            }
        }
    }
}

__global__ void __launch_bounds__(256, 2) gemm_qkv_gate(
    const __half* __restrict__ xn,  const __half* __restrict__ wq,
    const float* __restrict__ bq,   float* __restrict__ qkvC,
    const __half* __restrict__ x16, const __half* __restrict__ wg,
    const float* __restrict__ bg,   float* __restrict__ gateC)
{
    extern __shared__ char smem[];
    int bx = blockIdx.x, by = blockIdx.y;
    if (bx < N3D / 128) {
        gemm_core(smem, xn + (size_t)by * 128 * GK,
                  wq + (size_t)bx * 128 * GK, bq, qkvC, N3D, bx * 128, by * 128, 0);
    } else {
        int b2 = bx - N3D / 128;
        gemm_core(smem, x16 + (size_t)by * 128 * GK,
                  wg + (size_t)b2 * 128 * GK, bg, gateC, D2, b2 * 128, by * 128, 1);
    }
}

__global__ void __launch_bounds__(256, 2) gemm_proj(
    const __half* __restrict__ at16, const __half* __restrict__ wp,
    const float* __restrict__ bp,    float* __restrict__ outC)
{
    extern __shared__ char smem[];
    int bx = blockIdx.x, by = blockIdx.y;
    gemm_core(smem, at16 + (size_t)by * 128 * GK,
              wp + (size_t)bx * 128 * GK, bp, outC, D2, bx * 128, by * 128, 0);
}

// ---------------- prep -> fp16 q/k/v in head layout ------------------------
__global__ void prep_kernel(const float* __restrict__ qkv,
                            const float* __restrict__ gate,
                            __half* __restrict__ qf,
                            __half* __restrict__ kf,
                            __half* __restrict__ vf) {
    int idx = blockIdx.x * 256 + threadIdx.x;
    int bl = idx / D2;
    int c  = idx - bl * D2;
    int h = c >> 6, d = c & 63;
    int b = bl >> 10, l = bl & 1023;
    float q = qkv[(size_t)bl * N3D + c];
    float k = qkv[(size_t)bl * N3D + D2 + c] * gate[idx];
    float v = qkv[(size_t)bl * N3D + 2 * D2 + c];
    int o = ((b * H2 + h) * L2 + l) * DH + d;
    qf[o] = __float2half_rn((q > 0.f) ? (q + 1.f) : expf(q));
    kf[o] = __float2half_rn((k > 0.f) ? (k + 1.f) : expf(k));
    vf[o] = v;  // implicit float->half? no: explicit below
    vf[o] = __float2half_rn(v);
}

// ---------------- per-chunk K^T V via MMA + ksum ---------------------------
// Kt/Vt: 64 rows x 136 halves (272B stride, 16B aligned)
__global__ void chunk_kv_kernel(const __half* __restrict__ kf,
                                const __half* __restrict__ vf,
                                float* __restrict__ kv,
                                float* __restrict__ ksum) {
    __shared__ __half sm2[2 * 64 * 136];
    __half* Kt = sm2;
    __half* Vt = sm2 + 64 * 136;
    int c = blockIdx.x, bh = blockIdx.y;
    int tid = threadIdx.x;   // 256
    int wid = tid >> 5, lane = tid & 31;
    const __half* kp = kf + (size_t)(bh * L2 + c * CHK) * DH;
    const __half* vp = vf + (size_t)(bh * L2 + c * CHK) * DH;
    // transpose loads: Kt[d][t] = K[t][d]
    for (int i = tid; i < CHK * DH; i += 256) {
        int t = i >> 6, d = i & 63;
        Kt[d * 136 + t] = kp[t * DH + d];
        Vt[d * 136 + t] = vp[t * DH + d];
    }
    __syncthreads();

    uint32_t sb = smem_u32(sm2);
    uint32_t vtb = sb + 64 * 136 * 2;
    int lr = lane & 7, g = lane >> 3;
    int arow = ((g & 1) << 3) + lr;
    int acolb = (g >> 1) << 4;
    int brow = ((g >> 1) << 3) + lr;
    int bcolb = (g & 1) << 4;
    int wm = wid >> 2, wn = wid & 3;
    int m0 = wm * 32, n0 = wn * 16;

    float acc[2][2][4];
    #pragma unroll
    for (int mt = 0; mt < 2; mt++)
        #pragma unroll
        for (int nt = 0; nt < 2; nt++)
            #pragma unroll
            for (int q = 0; q < 4; q++) acc[mt][nt][q] = 0.f;

    #pragma unroll
    for (int kt = 0; kt < 8; kt++) {
        uint32_t bf[2][2];
        uint32_t baddr = vtb + (uint32_t)((n0 + brow) * 272 + kt * 32 + bcolb);
        LDSM4(bf[0][0], bf[0][1], bf[1][0], bf[1][1], baddr);
        #pragma unroll
        for (int mt = 0; mt < 2; mt++) {
            uint32_t aaddr = sb + (uint32_t)((m0 + mt * 16 + arow) * 272 + kt * 32 + acolb);
            uint32_t af[4];
            LDSM4(af[0], af[1], af[2], af[3], aaddr);
            #pragma unroll
            for (int nt = 0; nt < 2; nt++)
                MMA_F16(acc[mt][nt], af, bf[nt]);
        }
    }

    float* kvp = kv + (size_t)(bh * NC + c) * DH * DH;
    int r0 = lane >> 2, cpair = (lane & 3) << 1;
    #pragma unroll
    for (int mt = 0; mt < 2; mt++)
        #pragma unroll
        for (int nt = 0; nt < 2; nt++)
            #pragma unroll
            for (int h = 0; h < 2; h++) {
                int i = m0 + mt * 16 + r0 + 8 * h;
                int j = n0 + nt * 8 + cpair;
                *(float2*)(kvp + i * DH + j) =
                    make_float2(acc[mt][nt][2*h], acc[mt][nt][2*h + 1]);
            }
    // ksum: row sums of Kt
    if (tid < 64) {
        float s = 0.f;
        const __half2* kr = (const __half2*)(Kt + tid * 136);
        #pragma unroll
        for (int t = 0; t < 64; t++) {
            float2 f = __half22float2(kr[t]);
            s += f.x + f.y;
        }
        ksum[(bh * NC + c) * DH + tid] = s;
    }
}

// ---------------- exclusive prefix over chunks ----------------------------
__global__ void scan_kernel(const float* __restrict__ kv,
                            const float* __restrict__ ksum,
                            float* __restrict__ sprev,
                            float* __restrict__ ksp) {
    int bh = blockIdx.x;
    int tid = threadIdx.x;  // 256
    #pragma unroll
    for (int r = 0; r < 16; r++) {
        int e = tid + 256 * r;
        float acc = 0.f;
        #pragma unroll
        for (int c = 0; c < NC; c++) {
            size_t o = (size_t)(bh * NC + c) * DH * DH + e;
            sprev[o] = acc;
            acc += kv[o];
        }
    }
    if (tid < 64) {
        float acc = 0.f;
        #pragma unroll
        for (int c = 0; c < NC; c++) {
            size_t o = (size_t)(bh * NC + c) * DH + tid;
            ksp[o] = acc;
            acc += ksum[o];
        }
    }
}

// ---------------- per-chunk attention via MMA ------------------------------
// smem (halves): Q 128x72 @0 | K 128x72 @9216 | Vt 64x136 @18432 |
//                St 64x72 @27136 | Af 128x136 @31744 | floats @98304 (den128,ks64)
#define AQ   0
#define AK   9216
#define AVT  18432
#define AST  27136
#define AAF  31744
#define AFLB 98304
#define ATTN_SMEM_BYTES (AFLB + 768)

__global__ void __launch_bounds__(256) attn_kernel(
        const __half* __restrict__ qf,
        const __half* __restrict__ kf,
        const __half* __restrict__ vf,
        const float* __restrict__ sprev,
        const float* __restrict__ ksp,
        __half* __restrict__ ao16) {
    extern __shared__ __half smh[];
    float* flt = (float*)((char*)smh + AFLB);
    uint32_t sb = smem_u32(smh);
    int c = blockIdx.x, bh = blockIdx.y;
    int tid = threadIdx.x;   // 256
    int wid = tid >> 5, lane = tid & 31;
    const __half* qp = qf + (size_t)(bh * L2 + c * CHK) * DH;
    const __half* kp = kf + (size_t)(bh * L2 + c * CHK) * DH;
    const __half* vp = vf + (size_t)(bh * L2 + c * CHK) * DH;
    const float* sp  = sprev + (size_t)(bh * NC + c) * DH * DH;

    // loads: Q,K direct (uint4), V transpose, S transpose, ksum
    for (int i = tid; i < 1024; i += 256) {
        int row = i >> 3, seg = i & 7;
        *(uint4*)(smh + AQ + row * 72 + seg * 8) = *(const uint4*)(qp + row * DH + seg * 8);
        *(uint4*)(smh + AK + row * 72 + seg * 8) = *(const uint4*)(kp + row * DH + seg * 8);
    }
    for (int i = tid; i < CHK * DH; i += 256) {
        int t = i >> 6, j = i & 63;
        smh[AVT + j * 136 + t] = vp[t * DH + j];
    }
    for (int i = tid; i < DH * DH; i += 256) {
        int d = i >> 6, e = i & 63;
        smh[AST + e * 72 + d] = __float2half_rn(sp[d * DH + e]);
    }
    if (tid < 64) flt[128 + tid] = ksp[(bh * NC + c) * DH + tid];
    __syncthreads();

    int lr = lane & 7, g = lane >> 3;
    int arow = ((g & 1) << 3) + lr;
    int acolb = (g >> 1) << 4;
    int brow = ((g >> 1) << 3) + lr;
    int bcolb = (g & 1) << 4;
    int r0 = lane >> 2, cpair = (lane & 3) << 1;

    // ---- phase 2: A = QK^T (dense) -> mask -> fp16 Af ----
    {
        int wm = wid >> 2, wn = wid & 3;
        int m0 = wm * 64, n0 = wn * 32;
        float qa[4][4][4];
        #pragma unroll
        for (int mt = 0; mt < 4; mt++)
            #pragma unroll
            for (int nt = 0; nt < 4; nt++)
                #pragma unroll
                for (int q = 0; q < 4; q++) qa[mt][nt][q] = 0.f;
        #pragma unroll
        for (int kt = 0; kt < 4; kt++) {
            uint32_t bf[4][2];
            #pragma unroll
            for (int t = 0; t < 2; t++) {
                uint32_t baddr = sb + AK * 2 + (uint32_t)((n0 + t * 16 + brow) * 144 + kt * 32 + bcolb);
                LDSM4(bf[2*t][0], bf[2*t][1], bf[2*t+1][0], bf[2*t+1][1], baddr);
            }
            #pragma unroll
            for (int mt = 0; mt < 4; mt++) {
                uint32_t aaddr = sb + AQ * 2 + (uint32_t)((m0 + mt * 16 + arow) * 144 + kt * 32 + acolb);
                uint32_t af[4];
                LDSM4(af[0], af[1], af[2], af[3], aaddr);
                #pragma unroll
                for (int nt = 0; nt < 4; nt++)
                    MMA_F16(qa[mt][nt], af, bf[nt]);
            }
        }
        #pragma unroll
        for (int mt = 0; mt < 4; mt++)
            #pragma unroll
            for (int nt = 0; nt < 4; nt++)
                #pragma unroll
                for (int h = 0; h < 2; h++) {
                    int ai = m0 + mt * 16 + r0 + 8 * h;
                    int aj = n0 + nt * 8 + cpair;
                    float v0 = (aj     <= ai) ? qa[mt][nt][2*h]     : 0.f;
                    float v1 = (aj + 1 <= ai) ? qa[mt][nt][2*h + 1] : 0.f;
                    *(__half2*)(smh + AAF + ai * 136 + aj) = __floats2half2_rn(v0, v1);
                }
    }
    __syncthreads();

    // ---- denominators ----
    if (tid < 128) {
        float s = 0.f;
        const __half2* ar = (const __half2*)(smh + AAF + tid * 136);
        #pragma unroll
        for (int jj = 0; jj < 64; jj++) {
            float2 f = __half22float2(ar[jj]);
            s += f.x + f.y;
        }
        const __half* qr = smh + AQ + tid * 72;
        float qk = 0.f;
        #pragma unroll
        for (int d = 0; d < 64; d++)
            qk += __half2float(qr[d]) * flt[128 + d];
        flt[tid] = s + qk + 1e-6f;
    }
    __syncthreads();

    // ---- phase 3: O = Af@V + Q@S_prev; divide; write fp16 ----
    {
        int wm2 = wid >> 1, wn2 = wid & 1;
        int m0 = wm2 * 32, n0 = wn2 * 32;
        float oa[2][4][4];
        #pragma unroll
        for (int mt = 0; mt < 2; mt++)
            #pragma unroll
            for (int nt = 0; nt < 4; nt++)
                #pragma unroll
                for (int q = 0; q < 4; q++) oa[mt][nt][q] = 0.f;
        // Af @ V  (k = 128)
        #pragma unroll
        for (int kt = 0; kt < 8; kt++) {
            uint32_t bf[4][2];
            #pragma unroll
            for (int t = 0; t < 2; t++) {
                uint32_t baddr = sb + AVT * 2 + (uint32_t)((n0 + t * 16 + brow) * 272 + kt * 32 + bcolb);
                LDSM4(bf[2*t][0], bf[2*t][1], bf[2*t+1][0], bf[2*t+1][1], baddr);
            }
            #pragma unroll
            for (int mt = 0; mt < 2; mt++) {
                uint32_t aaddr = sb + AAF * 2 + (uint32_t)((m0 + mt * 16 + arow) * 272 + kt * 32 + acolb);
                uint32_t af[4];
                LDSM4(af[0], af[1], af[2], af[3], aaddr);
                #pragma unroll
                for (int nt = 0; nt < 4; nt++)
                    MMA_F16(oa[mt][nt], af, bf[nt]);
            }
        }
        // Q @ S_prev  (k = 64)
        #pragma unroll
        for (int kt = 0; kt < 4; kt++) {
            uint32_t bf[4][2];
            #pragma unroll
            for (int t = 0; t < 2; t++) {
                uint32_t baddr = sb + AST * 2 + (uint32_t)((n0 + t * 16 + brow) * 144 + kt * 32 + bcolb);
                LDSM4(bf[2*t][0], bf[2*t][1], bf[2*t+1][0], bf[2*t+1][1], baddr);
            }
            #pragma unroll
            for (int mt = 0; mt < 2; mt++) {
                uint32_t aaddr = sb + AQ * 2 + (uint32_t)((m0 + mt * 16 + arow) * 144 + kt * 32 + acolb);
                uint32_t af[4];
                LDSM4(af[0], af[1], af[2], af[3], aaddr);
                #pragma unroll
                for (int nt = 0; nt < 4; nt++)
                    MMA_F16(oa[mt][nt], af, bf[nt]);
            }
        }
        int b = bh / H2, hh = bh - b * H2;
        #pragma unroll
        for (int mt = 0; mt < 2; mt++)
            #pragma unroll
            for (int nt = 0; nt < 4; nt++)
                #pragma unroll
                for (int h = 0; h < 2; h++) {
                    int oi = m0 + mt * 16 + r0 + 8 * h;
                    int oj = n0 + nt * 8 + cpair;
                    float dv = flt[oi];
                    float w0 = oa[mt][nt][2*h]     / dv;
                    float w1 = oa[mt][nt][2*h + 1] / dv;
                    int l = c * CHK + oi;
                    *(__half2*)(ao16 + (size_t)(b * L2 + l) * D2 + hh * DH + oj) =
                        __floats2half2_rn(w0, w1);
                }
    }
}

// ---------------- launch ---------------------------------------------------
extern "C" void kernel_launch(void* const* d_in, const int* in_sizes, int n_in,
                              void* d_out, int out_size) {
    const float* x      = (const float*)d_in[0];
    const float* W_qkv  = (const float*)d_in[1];
    const float* b_qkv  = (const float*)d_in[2];
    const float* W_gate = (const float*)d_in[3];
    const float* b_gate = (const float*)d_in[4];
    const float* W_proj = (const float*)d_in[5];
    const float* b_proj = (const float*)d_in[6];
    const float* ln_g   = (const float*)d_in[7];
    const float* ln_b   = (const float*)d_in[8];
    float* out  = (float*)d_out;           // proj output
    float* gate = out + OUT_ELEMS;         // gate output (2nd return value)

    float *p_qkv, *p_kv, *p_ksum, *p_sprev, *p_ksp;
    __half *p_an, *p_x16, *p_at16, *p_wtq, *p_wtg, *p_wtp;
    __half *p_qf16, *p_kf16, *p_vf16;
    cudaGetSymbolAddress((void**)&p_qkv,   g_qkv);
    cudaGetSymbolAddress((void**)&p_kv,    g_kv);
    cudaGetSymbolAddress((void**)&p_ksum,  g_ksum);
    cudaGetSymbolAddress((void**)&p_sprev, g_sprev);
    cudaGetSymbolAddress((void**)&p_ksp,   g_ksp);
    cudaGetSymbolAddress((void**)&p_an,    g_an);
    cudaGetSymbolAddress((void**)&p_x16,   g_x16);
    cudaGetSymbolAddress((void**)&p_at16,  g_at16);
    cudaGetSymbolAddress((void**)&p_wtq,   g_wtq);
    cudaGetSymbolAddress((void**)&p_wtg,   g_wtg);
    cudaGetSymbolAddress((void**)&p_wtp,   g_wtp);
    cudaGetSymbolAddress((void**)&p_qf16,  g_qf16);
    cudaGetSymbolAddress((void**)&p_kf16,  g_kf16);
    cudaGetSymbolAddress((void**)&p_vf16,  g_vf16);

    cudaFuncSetAttribute(gemm_qkv_gate, cudaFuncAttributeMaxDynamicSharedMemorySize,
                         GEMM_SMEM_BYTES);
    cudaFuncSetAttribute(gemm_proj, cudaFuncAttributeMaxDynamicSharedMemorySize,
                         GEMM_SMEM_BYTES);
    cudaFuncSetAttribute(attn_kernel, cudaFuncAttributeMaxDynamicSharedMemorySize,
                         ATTN_SMEM_BYTES);

    // 0. transpose weights -> [N, K] fp16
    transpose_kernel<<<dim3(N3D / 32, GK / 32), dim3(32, 8)>>>(W_qkv, p_wtq, GK, N3D);
    transpose_kernel<<<dim3(D2  / 32, GK / 32), dim3(32, 8)>>>(W_gate, p_wtg, GK, D2);
    transpose_kernel<<<dim3(D2  / 32, GK / 32), dim3(32, 8)>>>(W_proj, p_wtp, GK, D2);

    // 1. LayerNorm -> fp16 xn and fp16 raw x
    ln_kernel<<<BL, 256>>>(x, ln_g, ln_b, p_an, p_x16);

    // 2+3. fused QKV + gate GEMMs
    gemm_qkv_gate<<<dim3(N3D / 128 + D2 / 128, BL / 128), 256, GEMM_SMEM_BYTES>>>(
        p_an, p_wtq, b_qkv, p_qkv,
        p_x16, p_wtg, b_gate, gate);

    // 4. split / gate-k / elu+1 / head layout -> fp16
    prep_kernel<<<(BL * D2) / 256, 256>>>(p_qkv, gate, p_qf16, p_kf16, p_vf16);

    // 5. per-chunk K^T V via MMA
    chunk_kv_kernel<<<dim3(NC, BH), 256>>>(p_kf16, p_vf16, p_kv, p_ksum);

    // 6. exclusive prefix over chunks
    scan_kernel<<<BH, 256>>>(p_kv, p_ksum, p_sprev, p_ksp);

    // 7. per-chunk attention via MMA
    attn_kernel<<<dim3(NC, BH), 256, ATTN_SMEM_BYTES>>>(
        p_qf16, p_kf16, p_vf16, p_sprev, p_ksp, p_at16);

    // 8. out = attn @ W_proj + b_proj
    gemm_proj<<<dim3(D2 / 128, BL / 128), 256, GEMM_SMEM_BYTES>>>(
        p_at16, p_wtp, b_proj, out);
}